// round 12
// baseline (speedup 1.0000x reference)
#include <cuda_runtime.h>
#include <cuda_bf16.h>
#include <math.h>

#define Dn   64
#define Rn   4
#define NMAX 100000
#define EMAX 1200000
#define SEGS (NMAX * Rn)
#define BSTR 68   // weight pair-row stride: banks (2q*68 + g)%32 = 8q+g -> conflict-free

// ---------------- scratch ----------------
__device__ int   g_deg[SEGS];
__device__ int   g_off[SEGS + 1];
__device__ int   g_cur[SEGS];
__device__ int   g_srcs[EMAX];
__device__ unsigned long long g_state[512];       // lookback scan state
__device__ __nv_bfloat162 g_S[(size_t)SEGS * (Dn / 2)];   // per-(node,rel) MEAN, bf16
__device__ __nv_bfloat162 g_xb[(size_t)NMAX * (Dn / 2)];  // bf16 mirror of x
__device__ __nv_bfloat162 g_g1b[(size_t)NMAX * (Dn / 2)]; // bf16 mirror of g1
__device__ float g_h1[(size_t)NMAX * Dn];
__device__ float g_g1[(size_t)NMAX * Dn];
__device__ float g_h2[(size_t)NMAX * Dn];

__device__ __forceinline__ float sigmoidf_(float v) {
    return 1.0f / (1.0f + __expf(-v));
}

__device__ __forceinline__ float2 b2f2(unsigned u) {
    __nv_bfloat162 t = *reinterpret_cast<__nv_bfloat162*>(&u);
    return __bfloat1622float2(t);
}

__device__ __forceinline__ unsigned packbf(float lo, float hi) {
    __nv_bfloat162 t = __float22bfloat162_rn(make_float2(lo, hi));
    return *reinterpret_cast<unsigned*>(&t);
}

__device__ __forceinline__ void mma_bf16(float d[4], const unsigned a[4], const unsigned b[2]) {
    asm volatile("mma.sync.aligned.m16n8k16.row.col.f32.bf16.bf16.f32 "
                 "{%0,%1,%2,%3}, {%4,%5,%6,%7}, {%8,%9}, {%0,%1,%2,%3};"
                 : "+f"(d[0]), "+f"(d[1]), "+f"(d[2]), "+f"(d[3])
                 : "r"(a[0]), "r"(a[1]), "r"(a[2]), "r"(a[3]), "r"(b[0]), "r"(b[1]));
}

// ---------------- fp32 -> bf16x2 mirror ----------------
__global__ void f2b_kernel(const float* __restrict__ in, __nv_bfloat162* __restrict__ out, int n2) {
    int i = blockIdx.x * 256 + threadIdx.x;
    if (i < n2) {
        float2 v = reinterpret_cast<const float2*>(in)[i];
        out[i] = __float22bfloat162_rn(v);
    }
}

// ---------------- CSR build ----------------
__global__ void zero_deg_kernel() {
    int i = blockIdx.x * blockDim.x + threadIdx.x;
    if (i < SEGS) g_deg[i] = 0;
    if (i < 512) g_state[i] = 0ULL;
}

__global__ void hist_kernel(const int* __restrict__ dst, const int* __restrict__ rel, int E) {
    int e = blockIdx.x * blockDim.x + threadIdx.x;
    if (e < E) atomicAdd(&g_deg[dst[e] * Rn + rel[e]], 1);
}

// single-pass exclusive scan with decoupled lookback: g_deg -> g_off (+g_cur)
__global__ void __launch_bounds__(1024) scan_lb_kernel(int n) {
    __shared__ int wsum[32];
    __shared__ int s_prefix;
    int bid = blockIdx.x;
    int i = bid * 1024 + threadIdx.x;
    int lane = threadIdx.x & 31, wid = threadIdx.x >> 5;
    int v = (i < n) ? g_deg[i] : 0;
    int s = v;
#pragma unroll
    for (int d = 1; d < 32; d <<= 1) {
        int t = __shfl_up_sync(0xffffffffu, s, d);
        if (lane >= d) s += t;
    }
    if (lane == 31) wsum[wid] = s;
    __syncthreads();
    if (wid == 0) {
        int t = wsum[lane];
#pragma unroll
        for (int d = 1; d < 32; d <<= 1) {
            int u = __shfl_up_sync(0xffffffffu, t, d);
            if (lane >= d) t += u;
        }
        wsum[lane] = t;
    }
    __syncthreads();
    int add = (wid > 0) ? wsum[wid - 1] : 0;
    int inc = s + add;               // block-inclusive
    int agg = wsum[31];              // block total

    if (threadIdx.x == 0) {
        if (bid == 0) {
            atomicExch(&g_state[0], (2ULL << 32) | (unsigned)agg);
            s_prefix = 0;
        } else {
            atomicExch(&g_state[bid], (1ULL << 32) | (unsigned)agg);
            int run = 0;
            int j = bid - 1;
            while (true) {
                unsigned long long st;
                do { st = atomicAdd(&g_state[j], 0ULL); } while ((st >> 32) == 0ULL);
                run += (int)(unsigned)st;
                if ((st >> 32) == 2ULL) break;
                j--;
            }
            atomicExch(&g_state[bid], (2ULL << 32) | (unsigned)(run + agg));
            s_prefix = run;
        }
    }
    __syncthreads();
    int off = s_prefix + inc - v;    // exclusive global
    if (i < n) { g_off[i] = off; g_cur[i] = off; }
    if (i == n - 1) g_off[n] = off + v;
}

__global__ void scatter_kernel(const int* __restrict__ src, const int* __restrict__ dst,
                               const int* __restrict__ rel, int E) {
    int e = blockIdx.x * blockDim.x + threadIdx.x;
    if (e >= E) return;
    int seg = dst[e] * Rn + rel[e];
    int p = atomicAdd(&g_cur[seg], 1);
    g_srcs[p] = src[e];
}

// ---------------- aggregate: S[seg] = MEAN over edges of xb[src] ----------------
// 8 lanes per segment, uint4 (16B = 8 bf16) per lane.
__global__ void __launch_bounds__(256) aggregate_kernel(const __nv_bfloat162* __restrict__ xb) {
    int t = blockIdx.x * 256 + threadIdx.x;
    int seg = t >> 3;
    int lane = t & 7;
    if (seg >= SEGS) return;
    const uint4* rows = reinterpret_cast<const uint4*>(xb);
    int e0 = __ldg(&g_off[seg]);
    int e1 = __ldg(&g_off[seg + 1]);
    float a0 = 0.f, a1 = 0.f, a2 = 0.f, a3 = 0.f;
    float a4 = 0.f, a5 = 0.f, a6 = 0.f, a7 = 0.f;
    int e = e0;
    for (; e + 3 < e1; e += 4) {
        int s0 = __ldg(&g_srcs[e]);
        int s1 = __ldg(&g_srcs[e + 1]);
        int s2 = __ldg(&g_srcs[e + 2]);
        int s3 = __ldg(&g_srcs[e + 3]);
        uint4 u0 = __ldg(&rows[(size_t)s0 * 8 + lane]);
        uint4 u1 = __ldg(&rows[(size_t)s1 * 8 + lane]);
        uint4 u2 = __ldg(&rows[(size_t)s2 * 8 + lane]);
        uint4 u3 = __ldg(&rows[(size_t)s3 * 8 + lane]);
        float2 p;
        p = b2f2(u0.x); a0 += p.x; a1 += p.y;
        p = b2f2(u0.y); a2 += p.x; a3 += p.y;
        p = b2f2(u0.z); a4 += p.x; a5 += p.y;
        p = b2f2(u0.w); a6 += p.x; a7 += p.y;
        p = b2f2(u1.x); a0 += p.x; a1 += p.y;
        p = b2f2(u1.y); a2 += p.x; a3 += p.y;
        p = b2f2(u1.z); a4 += p.x; a5 += p.y;
        p = b2f2(u1.w); a6 += p.x; a7 += p.y;
        p = b2f2(u2.x); a0 += p.x; a1 += p.y;
        p = b2f2(u2.y); a2 += p.x; a3 += p.y;
        p = b2f2(u2.z); a4 += p.x; a5 += p.y;
        p = b2f2(u2.w); a6 += p.x; a7 += p.y;
        p = b2f2(u3.x); a0 += p.x; a1 += p.y;
        p = b2f2(u3.y); a2 += p.x; a3 += p.y;
        p = b2f2(u3.z); a4 += p.x; a5 += p.y;
        p = b2f2(u3.w); a6 += p.x; a7 += p.y;
    }
    for (; e < e1; e++) {
        int s0 = __ldg(&g_srcs[e]);
        uint4 u0 = __ldg(&rows[(size_t)s0 * 8 + lane]);
        float2 p;
        p = b2f2(u0.x); a0 += p.x; a1 += p.y;
        p = b2f2(u0.y); a2 += p.x; a3 += p.y;
        p = b2f2(u0.z); a4 += p.x; a5 += p.y;
        p = b2f2(u0.w); a6 += p.x; a7 += p.y;
    }
    int d = e1 - e0;
    float inv = 1.0f / (float)(d > 1 ? d : 1);
    uint4 o;
    o.x = packbf(a0 * inv, a1 * inv);
    o.y = packbf(a2 * inv, a3 * inv);
    o.z = packbf(a4 * inv, a5 * inv);
    o.w = packbf(a6 * inv, a7 * inv);
    reinterpret_cast<uint4*>(g_S)[(size_t)seg * 8 + lane] = o;
}

// ---------------- conv via bf16 m16n8k16 mma ----------------
// 256 threads / 8 warps, 32 nodes per warp -> 256 nodes per block.
__global__ void __launch_bounds__(256)
conv_mma_kernel(const __nv_bfloat162* __restrict__ xb,
                const __nv_bfloat162* __restrict__ S,
                const float* __restrict__ w,   // [64][256]
                const float* __restrict__ b,
                const float* __restrict__ ws,  // [64][64]
                const float* __restrict__ bs,
                float* __restrict__ out,
                int N) {
    extern __shared__ unsigned smu[];
    unsigned* sw = smu;                           // 160 pair-rows * BSTR
    float* sb = (float*)(smu + 160 * BSTR);       // 64
    int tid = threadIdx.x;

    for (int idx = tid; idx < Dn * 128; idx += 256) {
        int j = idx >> 7, kp = idx & 127;
        float2 v = *reinterpret_cast<const float2*>(w + j * 256 + 2 * kp);
        sw[kp * BSTR + j] = packbf(v.x, v.y);
    }
    for (int idx = tid; idx < Dn * 32; idx += 256) {
        int j = idx >> 5, kp = idx & 31;
        float2 v = *reinterpret_cast<const float2*>(ws + j * 64 + 2 * kp);
        sw[(128 + kp) * BSTR + j] = packbf(v.x, v.y);
    }
    if (tid < Dn) sb[tid] = b[tid] + bs[tid];
    __syncthreads();

    int lane = tid & 31, warp = tid >> 5;
    int g = lane >> 2, q = lane & 3;
    int mbase = blockIdx.x * 256 + warp * 32;

    int r0 = mbase + g, r1 = r0 + 8, r2 = r0 + 16, r3 = r0 + 24;
    int cr0 = min(r0, N - 1), cr1 = min(r1, N - 1);
    int cr2 = min(r2, N - 1), cr3 = min(r3, N - 1);

    float acc[2][8][4];
#pragma unroll
    for (int mt = 0; mt < 2; mt++)
#pragma unroll
        for (int n = 0; n < 8; n++)
#pragma unroll
            for (int i = 0; i < 4; i++) acc[mt][n][i] = 0.f;

    const uint2* S0 = reinterpret_cast<const uint2*>(S + (size_t)cr0 * 128);
    const uint2* S1 = reinterpret_cast<const uint2*>(S + (size_t)cr1 * 128);
    const uint2* S2 = reinterpret_cast<const uint2*>(S + (size_t)cr2 * 128);
    const uint2* S3 = reinterpret_cast<const uint2*>(S + (size_t)cr3 * 128);

#pragma unroll 2
    for (int kw = 0; kw < 16; kw++) {
        int ui = kw * 4 + q;
        uint2 U0 = S0[ui], U1 = S1[ui], U2 = S2[ui], U3 = S3[ui];
        unsigned a0[4] = { U0.x, U1.x, U0.y, U1.y };
        unsigned a1[4] = { U2.x, U3.x, U2.y, U3.y };
        const unsigned* w0 = sw + (kw * 8 + 2 * q) * BSTR + g;
#pragma unroll
        for (int n = 0; n < 8; n++) {
            unsigned bb[2] = { w0[n * 8], w0[BSTR + n * 8] };
            mma_bf16(acc[0][n], a0, bb);
            mma_bf16(acc[1][n], a1, bb);
        }
    }

    const uint2* X0 = reinterpret_cast<const uint2*>(xb + (size_t)cr0 * 32);
    const uint2* X1 = reinterpret_cast<const uint2*>(xb + (size_t)cr1 * 32);
    const uint2* X2 = reinterpret_cast<const uint2*>(xb + (size_t)cr2 * 32);
    const uint2* X3 = reinterpret_cast<const uint2*>(xb + (size_t)cr3 * 32);
#pragma unroll
    for (int kw = 0; kw < 4; kw++) {
        int ui = kw * 4 + q;
        uint2 U0 = X0[ui], U1 = X1[ui], U2 = X2[ui], U3 = X3[ui];
        unsigned a0[4] = { U0.x, U1.x, U0.y, U1.y };
        unsigned a1[4] = { U2.x, U3.x, U2.y, U3.y };
        const unsigned* w0 = sw + (128 + kw * 8 + 2 * q) * BSTR + g;
#pragma unroll
        for (int n = 0; n < 8; n++) {
            unsigned bb[2] = { w0[n * 8], w0[BSTR + n * 8] };
            mma_bf16(acc[0][n], a0, bb);
            mma_bf16(acc[1][n], a1, bb);
        }
    }

#pragma unroll
    for (int n = 0; n < 8; n++) {
        int col = n * 8 + 2 * q;
        float b0v = sb[col], b1v = sb[col + 1];
        if (r0 < N) {
            float2 o = { sigmoidf_(acc[0][n][0] + b0v), sigmoidf_(acc[0][n][1] + b1v) };
            *reinterpret_cast<float2*>(out + (size_t)r0 * Dn + col) = o;
        }
        if (r1 < N) {
            float2 o = { sigmoidf_(acc[0][n][2] + b0v), sigmoidf_(acc[0][n][3] + b1v) };
            *reinterpret_cast<float2*>(out + (size_t)r1 * Dn + col) = o;
        }
        if (r2 < N) {
            float2 o = { sigmoidf_(acc[1][n][0] + b0v), sigmoidf_(acc[1][n][1] + b1v) };
            *reinterpret_cast<float2*>(out + (size_t)r2 * Dn + col) = o;
        }
        if (r3 < N) {
            float2 o = { sigmoidf_(acc[1][n][2] + b0v), sigmoidf_(acc[1][n][3] + b1v) };
            *reinterpret_cast<float2*>(out + (size_t)r3 * Dn + col) = o;
        }
    }
}

// ---------------- highway via bf16 m16n8k16 mma ----------------
// 256 threads / 8 warps, 16 nodes per warp -> 128 nodes per block.
// A-frags converted inline from fp32 h / prev rows; blend reads fp32 h.
__global__ void __launch_bounds__(256)
highway_mma_kernel(const float* __restrict__ h,
                   const float* __restrict__ prev,
                   const float* __restrict__ pw,   // [64][128]
                   const float* __restrict__ pb,
                   const float* __restrict__ tw,   // [64][128]
                   const float* __restrict__ tb,
                   float* __restrict__ out,
                   __nv_bfloat162* __restrict__ outb,
                   int N) {
    extern __shared__ unsigned smu[];
    unsigned* sp = smu;                            // 64 pair-rows * BSTR
    unsigned* st = sp + 64 * BSTR;                 // 64 pair-rows * BSTR
    float* sbp = (float*)(st + 64 * BSTR);         // 64
    float* sbt = sbp + Dn;                         // 64
    int tid = threadIdx.x;

    for (int idx = tid; idx < Dn * 64; idx += 256) {
        int j = idx >> 6, kp = idx & 63;
        float2 vp = *reinterpret_cast<const float2*>(pw + j * 128 + 2 * kp);
        float2 vt = *reinterpret_cast<const float2*>(tw + j * 128 + 2 * kp);
        sp[kp * BSTR + j] = packbf(vp.x, vp.y);
        st[kp * BSTR + j] = packbf(vt.x, vt.y);
    }
    if (tid < Dn) { sbp[tid] = pb[tid]; sbt[tid] = tb[tid]; }
    __syncthreads();

    int lane = tid & 31, warp = tid >> 5;
    int g = lane >> 2, q = lane & 3;
    int mbase = blockIdx.x * 128 + warp * 16;

    int r0 = mbase + g, r1 = r0 + 8;
    int cr0 = min(r0, N - 1), cr1 = min(r1, N - 1);

    float accP[8][4], accT[8][4];
#pragma unroll
    for (int n = 0; n < 8; n++)
#pragma unroll
        for (int i = 0; i < 4; i++) { accP[n][i] = 0.f; accT[n][i] = 0.f; }

    const float4* H0 = reinterpret_cast<const float4*>(h + (size_t)cr0 * Dn);
    const float4* H1 = reinterpret_cast<const float4*>(h + (size_t)cr1 * Dn);
    const float4* P0 = reinterpret_cast<const float4*>(prev + (size_t)cr0 * Dn);
    const float4* P1 = reinterpret_cast<const float4*>(prev + (size_t)cr1 * Dn);

#pragma unroll
    for (int kw = 0; kw < 4; kw++) {
        int ui = kw * 4 + q;
        float4 v0 = H0[ui], v1 = H1[ui];
        unsigned a[4] = { packbf(v0.x, v0.y), packbf(v1.x, v1.y),
                          packbf(v0.z, v0.w), packbf(v1.z, v1.w) };
        const unsigned* p0 = sp + (kw * 8 + 2 * q) * BSTR + g;
        const unsigned* t0 = st + (kw * 8 + 2 * q) * BSTR + g;
#pragma unroll
        for (int n = 0; n < 8; n++) {
            unsigned bp[2] = { p0[n * 8], p0[BSTR + n * 8] };
            unsigned bt[2] = { t0[n * 8], t0[BSTR + n * 8] };
            mma_bf16(accP[n], a, bp);
            mma_bf16(accT[n], a, bt);
        }
    }
#pragma unroll
    for (int kw = 0; kw < 4; kw++) {
        int ui = kw * 4 + q;
        float4 v0 = P0[ui], v1 = P1[ui];
        unsigned a[4] = { packbf(v0.x, v0.y), packbf(v1.x, v1.y),
                          packbf(v0.z, v0.w), packbf(v1.z, v1.w) };
        const unsigned* p0 = sp + (32 + kw * 8 + 2 * q) * BSTR + g;
        const unsigned* t0 = st + (32 + kw * 8 + 2 * q) * BSTR + g;
#pragma unroll
        for (int n = 0; n < 8; n++) {
            unsigned bp[2] = { p0[n * 8], p0[BSTR + n * 8] };
            unsigned bt[2] = { t0[n * 8], t0[BSTR + n * 8] };
            mma_bf16(accP[n], a, bp);
            mma_bf16(accT[n], a, bt);
        }
    }

#pragma unroll
    for (int n = 0; n < 8; n++) {
        int col = n * 8 + 2 * q;
        float bp0 = sbp[col], bp1 = sbp[col + 1];
        float bt0 = sbt[col], bt1 = sbt[col + 1];
        if (r0 < N) {
            float2 hv = *reinterpret_cast<const float2*>(h + (size_t)r0 * Dn + col);
            float pr0 = fmaxf(accP[n][0] + bp0, 0.f);
            float pr1 = fmaxf(accP[n][1] + bp1, 0.f);
            float g0 = sigmoidf_(accT[n][0] + bt0);
            float g1 = sigmoidf_(accT[n][1] + bt1);
            float2 o = { g0 * pr0 + (1.f - g0) * hv.x, g1 * pr1 + (1.f - g1) * hv.y };
            *reinterpret_cast<float2*>(out + (size_t)r0 * Dn + col) = o;
            if (outb) outb[((size_t)r0 * Dn + col) >> 1] = __float22bfloat162_rn(o);
        }
        if (r1 < N) {
            float2 hv = *reinterpret_cast<const float2*>(h + (size_t)r1 * Dn + col);
            float pr0 = fmaxf(accP[n][2] + bp0, 0.f);
            float pr1 = fmaxf(accP[n][3] + bp1, 0.f);
            float g0 = sigmoidf_(accT[n][2] + bt0);
            float g1 = sigmoidf_(accT[n][3] + bt1);
            float2 o = { g0 * pr0 + (1.f - g0) * hv.x, g1 * pr1 + (1.f - g1) * hv.y };
            *reinterpret_cast<float2*>(out + (size_t)r1 * Dn + col) = o;
            if (outb) outb[((size_t)r1 * Dn + col) >> 1] = __float22bfloat162_rn(o);
        }
    }
}

// ---------------- launch ----------------
extern "C" void kernel_launch(void* const* d_in, const int* in_sizes, int n_in,
                              void* d_out, int out_size) {
    const float* x    = (const float*)d_in[0];
    const int*   src  = (const int*)d_in[1];
    const int*   dst  = (const int*)d_in[2];
    const int*   rel  = (const int*)d_in[3];
    const float* c1w  = (const float*)d_in[4];
    const float* c1b  = (const float*)d_in[5];
    const float* c1ws = (const float*)d_in[6];
    const float* c1bs = (const float*)d_in[7];
    const float* h1pw = (const float*)d_in[8];
    const float* h1pb = (const float*)d_in[9];
    const float* h1tw = (const float*)d_in[10];
    const float* h1tb = (const float*)d_in[11];
    const float* c2w  = (const float*)d_in[12];
    const float* c2b  = (const float*)d_in[13];
    const float* c2ws = (const float*)d_in[14];
    const float* c2bs = (const float*)d_in[15];
    const float* h2pw = (const float*)d_in[16];
    const float* h2pb = (const float*)d_in[17];
    const float* h2tw = (const float*)d_in[18];
    const float* h2tb = (const float*)d_in[19];
    float* out = (float*)d_out;

    int N = in_sizes[0] / Dn;
    int E = in_sizes[1];

    __nv_bfloat162 *Sp, *xbp, *g1bp;
    float *h1p, *g1p, *h2p;
    cudaGetSymbolAddress((void**)&Sp, g_S);
    cudaGetSymbolAddress((void**)&xbp, g_xb);
    cudaGetSymbolAddress((void**)&g1bp, g_g1b);
    cudaGetSymbolAddress((void**)&h1p, g_h1);
    cudaGetSymbolAddress((void**)&g1p, g_g1);
    cudaGetSymbolAddress((void**)&h2p, g_h2);

    const int convSmem = 160 * BSTR * 4 + 64 * 4;
    const int hwSmem   = 2 * 64 * BSTR * 4 + 128 * 4;
    cudaFuncSetAttribute(conv_mma_kernel, cudaFuncAttributeMaxDynamicSharedMemorySize, convSmem);
    cudaFuncSetAttribute(highway_mma_kernel, cudaFuncAttributeMaxDynamicSharedMemorySize, hwSmem);

    int convGrid = (N + 255) / 256;
    int hwGrid   = (N + 127) / 128;
    int scanBlocks = (SEGS + 1023) / 1024;

    // ---- bf16 mirror of x + CSR build (graph identical in both layers) ----
    f2b_kernel<<<(N * 32 + 255) / 256, 256>>>(x, xbp, N * 32);
    zero_deg_kernel<<<(SEGS + 255) / 256, 256>>>();
    hist_kernel<<<(E + 255) / 256, 256>>>(dst, rel, E);
    scan_lb_kernel<<<scanBlocks, 1024>>>(SEGS);
    scatter_kernel<<<(E + 255) / 256, 256>>>(src, dst, rel, E);

    int aggGrid = SEGS / 32;   // 8 lanes per segment

    // ---- layer 1 ----
    aggregate_kernel<<<aggGrid, 256>>>(xbp);
    conv_mma_kernel<<<convGrid, 256, convSmem>>>(xbp, Sp, c1w, c1b, c1ws, c1bs, h1p, N);
    highway_mma_kernel<<<hwGrid, 256, hwSmem>>>(h1p, x, h1pw, h1pb, h1tw, h1tb, g1p, g1bp, N);

    // ---- layer 2 ----
    aggregate_kernel<<<aggGrid, 256>>>(g1bp);
    conv_mma_kernel<<<convGrid, 256, convSmem>>>(g1bp, Sp, c2w, c2b, c2ws, c2bs, h2p, N);
    highway_mma_kernel<<<hwGrid, 256, hwSmem>>>(h2p, h1p, h2pw, h2pb, h2tw, h2tb, out, nullptr, N);
}

// round 13
// speedup vs baseline: 1.0344x; 1.0344x over previous
#include <cuda_runtime.h>
#include <cuda_bf16.h>
#include <math.h>

#define Dn   64
#define Rn   4
#define NMAX 100000
#define EMAX 1200000
#define SEGS (NMAX * Rn)
#define BSTR 68   // weight pair-row stride: banks (2q*68 + g)%32 = 8q+g -> conflict-free

// ---------------- scratch ----------------
__device__ int   g_deg[SEGS];
__device__ int   g_off[SEGS + 1];
__device__ int   g_cur[SEGS];
__device__ int   g_srcs[EMAX];
__device__ unsigned long long g_state[512];       // lookback scan state
__device__ __nv_bfloat162 g_S[(size_t)SEGS * (Dn / 2)];   // per-(node,rel) MEAN, bf16
__device__ __nv_bfloat162 g_xb[(size_t)NMAX * (Dn / 2)];  // bf16 mirror of x
__device__ __nv_bfloat162 g_g1b[(size_t)NMAX * (Dn / 2)]; // bf16 mirror of g1
__device__ float g_h1[(size_t)NMAX * Dn];
__device__ float g_g1[(size_t)NMAX * Dn];
__device__ float g_h2[(size_t)NMAX * Dn];

__device__ __forceinline__ float sigmoidf_(float v) {
    return 1.0f / (1.0f + __expf(-v));
}

__device__ __forceinline__ float2 b2f2(unsigned u) {
    __nv_bfloat162 t = *reinterpret_cast<__nv_bfloat162*>(&u);
    return __bfloat1622float2(t);
}

__device__ __forceinline__ unsigned packbf(float lo, float hi) {
    __nv_bfloat162 t = __float22bfloat162_rn(make_float2(lo, hi));
    return *reinterpret_cast<unsigned*>(&t);
}

__device__ __forceinline__ void mma_bf16(float d[4], const unsigned a[4], const unsigned b[2]) {
    asm volatile("mma.sync.aligned.m16n8k16.row.col.f32.bf16.bf16.f32 "
                 "{%0,%1,%2,%3}, {%4,%5,%6,%7}, {%8,%9}, {%0,%1,%2,%3};"
                 : "+f"(d[0]), "+f"(d[1]), "+f"(d[2]), "+f"(d[3])
                 : "r"(a[0]), "r"(a[1]), "r"(a[2]), "r"(a[3]), "r"(b[0]), "r"(b[1]));
}

// ---------------- fused init: zero deg/state + fp32->bf16 mirror of x ----------------
__global__ void init_kernel(const float* __restrict__ in, __nv_bfloat162* __restrict__ out, int n2) {
    int i = blockIdx.x * 256 + threadIdx.x;
    if (i < SEGS) g_deg[i] = 0;
    if (i < 512) g_state[i] = 0ULL;
    if (i < n2) {
        float2 v = reinterpret_cast<const float2*>(in)[i];
        out[i] = __float22bfloat162_rn(v);
    }
}

__global__ void hist_kernel(const int* __restrict__ dst, const int* __restrict__ rel, int E) {
    int e = blockIdx.x * blockDim.x + threadIdx.x;
    if (e < E) atomicAdd(&g_deg[dst[e] * Rn + rel[e]], 1);
}

// single-pass exclusive scan, warp-parallel decoupled lookback: g_deg -> g_off (+g_cur)
__global__ void __launch_bounds__(1024) scan_lb_kernel(int n) {
    __shared__ int wsum[32];
    __shared__ int s_prefix;
    int bid = blockIdx.x;
    int i = bid * 1024 + threadIdx.x;
    int lane = threadIdx.x & 31, wid = threadIdx.x >> 5;
    int v = (i < n) ? g_deg[i] : 0;
    int s = v;
#pragma unroll
    for (int d = 1; d < 32; d <<= 1) {
        int t = __shfl_up_sync(0xffffffffu, s, d);
        if (lane >= d) s += t;
    }
    if (lane == 31) wsum[wid] = s;
    __syncthreads();
    if (wid == 0) {
        int t = wsum[lane];
#pragma unroll
        for (int d = 1; d < 32; d <<= 1) {
            int u = __shfl_up_sync(0xffffffffu, t, d);
            if (lane >= d) t += u;
        }
        wsum[lane] = t;
    }
    __syncthreads();
    int add = (wid > 0) ? wsum[wid - 1] : 0;
    int inc = s + add;               // block-inclusive
    int agg = wsum[31];              // block total

    if (bid == 0) {
        if (threadIdx.x == 0) {
            atomicExch(&g_state[0], (2ULL << 32) | (unsigned)agg);
            s_prefix = 0;
        }
    } else {
        if (threadIdx.x == 0)
            atomicExch(&g_state[bid], (1ULL << 32) | (unsigned)agg);
        if (wid == 0) {
            int run = 0;
            int winEnd = bid;        // window covers [winEnd-32, winEnd)
            bool done = false;
            while (!done) {
                int j = winEnd - 1 - lane;
                unsigned long long st;
                unsigned flag;
                if (j >= 0) {
                    do {
                        st = atomicAdd(&g_state[j], 0ULL);
                        flag = (unsigned)(st >> 32);
                    } while (flag == 0);
                } else {
                    st = 2ULL << 32;
                    flag = 2;
                }
                unsigned pm = __ballot_sync(0xffffffffu, flag == 2);
                int val;
                if (pm) {
                    int firstP = __ffs(pm) - 1;   // nearest PREFIX tile
                    val = (lane <= firstP) ? (int)(unsigned)st : 0;
                    done = true;
                } else {
                    val = (j >= 0) ? (int)(unsigned)st : 0;
                }
#pragma unroll
                for (int d = 16; d; d >>= 1)
                    val += __shfl_down_sync(0xffffffffu, val, d);
                if (lane == 0) run += val;
                winEnd -= 32;
            }
            if (lane == 0) {
                atomicExch(&g_state[bid], (2ULL << 32) | (unsigned)(run + agg));
                s_prefix = run;
            }
        }
    }
    __syncthreads();
    int off = s_prefix + inc - v;    // exclusive global
    if (i < n) { g_off[i] = off; g_cur[i] = off; }
    if (i == n - 1) g_off[n] = off + v;
}

__global__ void scatter_kernel(const int* __restrict__ src, const int* __restrict__ dst,
                               const int* __restrict__ rel, int E) {
    int e = blockIdx.x * blockDim.x + threadIdx.x;
    if (e >= E) return;
    int seg = dst[e] * Rn + rel[e];
    int p = atomicAdd(&g_cur[seg], 1);
    g_srcs[p] = src[e];
}

// ---------------- aggregate: S[seg] = MEAN over edges of xb[src] ----------------
// 8 lanes per segment, uint4 (16B = 8 bf16) per lane.
__global__ void __launch_bounds__(256) aggregate_kernel(const __nv_bfloat162* __restrict__ xb) {
    int t = blockIdx.x * 256 + threadIdx.x;
    int seg = t >> 3;
    int lane = t & 7;
    if (seg >= SEGS) return;
    const uint4* rows = reinterpret_cast<const uint4*>(xb);
    int e0 = __ldg(&g_off[seg]);
    int e1 = __ldg(&g_off[seg + 1]);
    float a0 = 0.f, a1 = 0.f, a2 = 0.f, a3 = 0.f;
    float a4 = 0.f, a5 = 0.f, a6 = 0.f, a7 = 0.f;
    int e = e0;
    for (; e + 3 < e1; e += 4) {
        int s0 = __ldg(&g_srcs[e]);
        int s1 = __ldg(&g_srcs[e + 1]);
        int s2 = __ldg(&g_srcs[e + 2]);
        int s3 = __ldg(&g_srcs[e + 3]);
        uint4 u0 = __ldg(&rows[(size_t)s0 * 8 + lane]);
        uint4 u1 = __ldg(&rows[(size_t)s1 * 8 + lane]);
        uint4 u2 = __ldg(&rows[(size_t)s2 * 8 + lane]);
        uint4 u3 = __ldg(&rows[(size_t)s3 * 8 + lane]);
        float2 p;
        p = b2f2(u0.x); a0 += p.x; a1 += p.y;
        p = b2f2(u0.y); a2 += p.x; a3 += p.y;
        p = b2f2(u0.z); a4 += p.x; a5 += p.y;
        p = b2f2(u0.w); a6 += p.x; a7 += p.y;
        p = b2f2(u1.x); a0 += p.x; a1 += p.y;
        p = b2f2(u1.y); a2 += p.x; a3 += p.y;
        p = b2f2(u1.z); a4 += p.x; a5 += p.y;
        p = b2f2(u1.w); a6 += p.x; a7 += p.y;
        p = b2f2(u2.x); a0 += p.x; a1 += p.y;
        p = b2f2(u2.y); a2 += p.x; a3 += p.y;
        p = b2f2(u2.z); a4 += p.x; a5 += p.y;
        p = b2f2(u2.w); a6 += p.x; a7 += p.y;
        p = b2f2(u3.x); a0 += p.x; a1 += p.y;
        p = b2f2(u3.y); a2 += p.x; a3 += p.y;
        p = b2f2(u3.z); a4 += p.x; a5 += p.y;
        p = b2f2(u3.w); a6 += p.x; a7 += p.y;
    }
    for (; e < e1; e++) {
        int s0 = __ldg(&g_srcs[e]);
        uint4 u0 = __ldg(&rows[(size_t)s0 * 8 + lane]);
        float2 p;
        p = b2f2(u0.x); a0 += p.x; a1 += p.y;
        p = b2f2(u0.y); a2 += p.x; a3 += p.y;
        p = b2f2(u0.z); a4 += p.x; a5 += p.y;
        p = b2f2(u0.w); a6 += p.x; a7 += p.y;
    }
    int d = e1 - e0;
    float inv = 1.0f / (float)(d > 1 ? d : 1);
    uint4 o;
    o.x = packbf(a0 * inv, a1 * inv);
    o.y = packbf(a2 * inv, a3 * inv);
    o.z = packbf(a4 * inv, a5 * inv);
    o.w = packbf(a6 * inv, a7 * inv);
    reinterpret_cast<uint4*>(g_S)[(size_t)seg * 8 + lane] = o;
}

// ---------------- conv via bf16 m16n8k16 mma ----------------
// 256 threads / 8 warps, 32 nodes per warp -> 256 nodes per block.
__global__ void __launch_bounds__(256)
conv_mma_kernel(const __nv_bfloat162* __restrict__ xb,
                const __nv_bfloat162* __restrict__ S,
                const float* __restrict__ w,   // [64][256]
                const float* __restrict__ b,
                const float* __restrict__ ws,  // [64][64]
                const float* __restrict__ bs,
                float* __restrict__ out,
                int N) {
    extern __shared__ unsigned smu[];
    unsigned* sw = smu;                           // 160 pair-rows * BSTR
    float* sb = (float*)(smu + 160 * BSTR);       // 64
    int tid = threadIdx.x;

    for (int idx = tid; idx < Dn * 128; idx += 256) {
        int j = idx >> 7, kp = idx & 127;
        float2 v = *reinterpret_cast<const float2*>(w + j * 256 + 2 * kp);
        sw[kp * BSTR + j] = packbf(v.x, v.y);
    }
    for (int idx = tid; idx < Dn * 32; idx += 256) {
        int j = idx >> 5, kp = idx & 31;
        float2 v = *reinterpret_cast<const float2*>(ws + j * 64 + 2 * kp);
        sw[(128 + kp) * BSTR + j] = packbf(v.x, v.y);
    }
    if (tid < Dn) sb[tid] = b[tid] + bs[tid];
    __syncthreads();

    int lane = tid & 31, warp = tid >> 5;
    int g = lane >> 2, q = lane & 3;
    int mbase = blockIdx.x * 256 + warp * 32;

    int r0 = mbase + g, r1 = r0 + 8, r2 = r0 + 16, r3 = r0 + 24;
    int cr0 = min(r0, N - 1), cr1 = min(r1, N - 1);
    int cr2 = min(r2, N - 1), cr3 = min(r3, N - 1);

    float acc[2][8][4];
#pragma unroll
    for (int mt = 0; mt < 2; mt++)
#pragma unroll
        for (int n = 0; n < 8; n++)
#pragma unroll
            for (int i = 0; i < 4; i++) acc[mt][n][i] = 0.f;

    const uint2* S0 = reinterpret_cast<const uint2*>(S + (size_t)cr0 * 128);
    const uint2* S1 = reinterpret_cast<const uint2*>(S + (size_t)cr1 * 128);
    const uint2* S2 = reinterpret_cast<const uint2*>(S + (size_t)cr2 * 128);
    const uint2* S3 = reinterpret_cast<const uint2*>(S + (size_t)cr3 * 128);

#pragma unroll 2
    for (int kw = 0; kw < 16; kw++) {
        int ui = kw * 4 + q;
        uint2 U0 = S0[ui], U1 = S1[ui], U2 = S2[ui], U3 = S3[ui];
        unsigned a0[4] = { U0.x, U1.x, U0.y, U1.y };
        unsigned a1[4] = { U2.x, U3.x, U2.y, U3.y };
        const unsigned* w0 = sw + (kw * 8 + 2 * q) * BSTR + g;
#pragma unroll
        for (int n = 0; n < 8; n++) {
            unsigned bb[2] = { w0[n * 8], w0[BSTR + n * 8] };
            mma_bf16(acc[0][n], a0, bb);
            mma_bf16(acc[1][n], a1, bb);
        }
    }

    const uint2* X0 = reinterpret_cast<const uint2*>(xb + (size_t)cr0 * 32);
    const uint2* X1 = reinterpret_cast<const uint2*>(xb + (size_t)cr1 * 32);
    const uint2* X2 = reinterpret_cast<const uint2*>(xb + (size_t)cr2 * 32);
    const uint2* X3 = reinterpret_cast<const uint2*>(xb + (size_t)cr3 * 32);
#pragma unroll
    for (int kw = 0; kw < 4; kw++) {
        int ui = kw * 4 + q;
        uint2 U0 = X0[ui], U1 = X1[ui], U2 = X2[ui], U3 = X3[ui];
        unsigned a0[4] = { U0.x, U1.x, U0.y, U1.y };
        unsigned a1[4] = { U2.x, U3.x, U2.y, U3.y };
        const unsigned* w0 = sw + (128 + kw * 8 + 2 * q) * BSTR + g;
#pragma unroll
        for (int n = 0; n < 8; n++) {
            unsigned bb[2] = { w0[n * 8], w0[BSTR + n * 8] };
            mma_bf16(acc[0][n], a0, bb);
            mma_bf16(acc[1][n], a1, bb);
        }
    }

#pragma unroll
    for (int n = 0; n < 8; n++) {
        int col = n * 8 + 2 * q;
        float b0v = sb[col], b1v = sb[col + 1];
        if (r0 < N) {
            float2 o = { sigmoidf_(acc[0][n][0] + b0v), sigmoidf_(acc[0][n][1] + b1v) };
            *reinterpret_cast<float2*>(out + (size_t)r0 * Dn + col) = o;
        }
        if (r1 < N) {
            float2 o = { sigmoidf_(acc[0][n][2] + b0v), sigmoidf_(acc[0][n][3] + b1v) };
            *reinterpret_cast<float2*>(out + (size_t)r1 * Dn + col) = o;
        }
        if (r2 < N) {
            float2 o = { sigmoidf_(acc[1][n][0] + b0v), sigmoidf_(acc[1][n][1] + b1v) };
            *reinterpret_cast<float2*>(out + (size_t)r2 * Dn + col) = o;
        }
        if (r3 < N) {
            float2 o = { sigmoidf_(acc[1][n][2] + b0v), sigmoidf_(acc[1][n][3] + b1v) };
            *reinterpret_cast<float2*>(out + (size_t)r3 * Dn + col) = o;
        }
    }
}

// ---------------- highway via bf16 m16n8k16 mma ----------------
// 256 threads / 8 warps, 16 nodes per warp -> 128 nodes per block.
// A-frags converted inline from fp32 h / prev rows; blend reads fp32 h.
__global__ void __launch_bounds__(256)
highway_mma_kernel(const float* __restrict__ h,
                   const float* __restrict__ prev,
                   const float* __restrict__ pw,   // [64][128]
                   const float* __restrict__ pb,
                   const float* __restrict__ tw,   // [64][128]
                   const float* __restrict__ tb,
                   float* __restrict__ out,
                   __nv_bfloat162* __restrict__ outb,
                   int N) {
    extern __shared__ unsigned smu[];
    unsigned* sp = smu;                            // 64 pair-rows * BSTR
    unsigned* st = sp + 64 * BSTR;                 // 64 pair-rows * BSTR
    float* sbp = (float*)(st + 64 * BSTR);         // 64
    float* sbt = sbp + Dn;                         // 64
    int tid = threadIdx.x;

    for (int idx = tid; idx < Dn * 64; idx += 256) {
        int j = idx >> 6, kp = idx & 63;
        float2 vp = *reinterpret_cast<const float2*>(pw + j * 128 + 2 * kp);
        float2 vt = *reinterpret_cast<const float2*>(tw + j * 128 + 2 * kp);
        sp[kp * BSTR + j] = packbf(vp.x, vp.y);
        st[kp * BSTR + j] = packbf(vt.x, vt.y);
    }
    if (tid < Dn) { sbp[tid] = pb[tid]; sbt[tid] = tb[tid]; }
    __syncthreads();

    int lane = tid & 31, warp = tid >> 5;
    int g = lane >> 2, q = lane & 3;
    int mbase = blockIdx.x * 128 + warp * 16;

    int r0 = mbase + g, r1 = r0 + 8;
    int cr0 = min(r0, N - 1), cr1 = min(r1, N - 1);

    float accP[8][4], accT[8][4];
#pragma unroll
    for (int n = 0; n < 8; n++)
#pragma unroll
        for (int i = 0; i < 4; i++) { accP[n][i] = 0.f; accT[n][i] = 0.f; }

    const float4* H0 = reinterpret_cast<const float4*>(h + (size_t)cr0 * Dn);
    const float4* H1 = reinterpret_cast<const float4*>(h + (size_t)cr1 * Dn);
    const float4* P0 = reinterpret_cast<const float4*>(prev + (size_t)cr0 * Dn);
    const float4* P1 = reinterpret_cast<const float4*>(prev + (size_t)cr1 * Dn);

#pragma unroll
    for (int kw = 0; kw < 4; kw++) {
        int ui = kw * 4 + q;
        float4 v0 = H0[ui], v1 = H1[ui];
        unsigned a[4] = { packbf(v0.x, v0.y), packbf(v1.x, v1.y),
                          packbf(v0.z, v0.w), packbf(v1.z, v1.w) };
        const unsigned* p0 = sp + (kw * 8 + 2 * q) * BSTR + g;
        const unsigned* t0 = st + (kw * 8 + 2 * q) * BSTR + g;
#pragma unroll
        for (int n = 0; n < 8; n++) {
            unsigned bp[2] = { p0[n * 8], p0[BSTR + n * 8] };
            unsigned bt[2] = { t0[n * 8], t0[BSTR + n * 8] };
            mma_bf16(accP[n], a, bp);
            mma_bf16(accT[n], a, bt);
        }
    }
#pragma unroll
    for (int kw = 0; kw < 4; kw++) {
        int ui = kw * 4 + q;
        float4 v0 = P0[ui], v1 = P1[ui];
        unsigned a[4] = { packbf(v0.x, v0.y), packbf(v1.x, v1.y),
                          packbf(v0.z, v0.w), packbf(v1.z, v1.w) };
        const unsigned* p0 = sp + (32 + kw * 8 + 2 * q) * BSTR + g;
        const unsigned* t0 = st + (32 + kw * 8 + 2 * q) * BSTR + g;
#pragma unroll
        for (int n = 0; n < 8; n++) {
            unsigned bp[2] = { p0[n * 8], p0[BSTR + n * 8] };
            unsigned bt[2] = { t0[n * 8], t0[BSTR + n * 8] };
            mma_bf16(accP[n], a, bp);
            mma_bf16(accT[n], a, bt);
        }
    }

#pragma unroll
    for (int n = 0; n < 8; n++) {
        int col = n * 8 + 2 * q;
        float bp0 = sbp[col], bp1 = sbp[col + 1];
        float bt0 = sbt[col], bt1 = sbt[col + 1];
        if (r0 < N) {
            float2 hv = *reinterpret_cast<const float2*>(h + (size_t)r0 * Dn + col);
            float pr0 = fmaxf(accP[n][0] + bp0, 0.f);
            float pr1 = fmaxf(accP[n][1] + bp1, 0.f);
            float g0 = sigmoidf_(accT[n][0] + bt0);
            float g1 = sigmoidf_(accT[n][1] + bt1);
            float2 o = { g0 * pr0 + (1.f - g0) * hv.x, g1 * pr1 + (1.f - g1) * hv.y };
            *reinterpret_cast<float2*>(out + (size_t)r0 * Dn + col) = o;
            if (outb) outb[((size_t)r0 * Dn + col) >> 1] = __float22bfloat162_rn(o);
        }
        if (r1 < N) {
            float2 hv = *reinterpret_cast<const float2*>(h + (size_t)r1 * Dn + col);
            float pr0 = fmaxf(accP[n][2] + bp0, 0.f);
            float pr1 = fmaxf(accP[n][3] + bp1, 0.f);
            float g0 = sigmoidf_(accT[n][2] + bt0);
            float g1 = sigmoidf_(accT[n][3] + bt1);
            float2 o = { g0 * pr0 + (1.f - g0) * hv.x, g1 * pr1 + (1.f - g1) * hv.y };
            *reinterpret_cast<float2*>(out + (size_t)r1 * Dn + col) = o;
            if (outb) outb[((size_t)r1 * Dn + col) >> 1] = __float22bfloat162_rn(o);
        }
    }
}

// ---------------- launch ----------------
extern "C" void kernel_launch(void* const* d_in, const int* in_sizes, int n_in,
                              void* d_out, int out_size) {
    const float* x    = (const float*)d_in[0];
    const int*   src  = (const int*)d_in[1];
    const int*   dst  = (const int*)d_in[2];
    const int*   rel  = (const int*)d_in[3];
    const float* c1w  = (const float*)d_in[4];
    const float* c1b  = (const float*)d_in[5];
    const float* c1ws = (const float*)d_in[6];
    const float* c1bs = (const float*)d_in[7];
    const float* h1pw = (const float*)d_in[8];
    const float* h1pb = (const float*)d_in[9];
    const float* h1tw = (const float*)d_in[10];
    const float* h1tb = (const float*)d_in[11];
    const float* c2w  = (const float*)d_in[12];
    const float* c2b  = (const float*)d_in[13];
    const float* c2ws = (const float*)d_in[14];
    const float* c2bs = (const float*)d_in[15];
    const float* h2pw = (const float*)d_in[16];
    const float* h2pb = (const float*)d_in[17];
    const float* h2tw = (const float*)d_in[18];
    const float* h2tb = (const float*)d_in[19];
    float* out = (float*)d_out;

    int N = in_sizes[0] / Dn;
    int E = in_sizes[1];

    __nv_bfloat162 *Sp, *xbp, *g1bp;
    float *h1p, *g1p, *h2p;
    cudaGetSymbolAddress((void**)&Sp, g_S);
    cudaGetSymbolAddress((void**)&xbp, g_xb);
    cudaGetSymbolAddress((void**)&g1bp, g_g1b);
    cudaGetSymbolAddress((void**)&h1p, g_h1);
    cudaGetSymbolAddress((void**)&g1p, g_g1);
    cudaGetSymbolAddress((void**)&h2p, g_h2);

    const int convSmem = 160 * BSTR * 4 + 64 * 4;
    const int hwSmem   = 2 * 64 * BSTR * 4 + 128 * 4;
    cudaFuncSetAttribute(conv_mma_kernel, cudaFuncAttributeMaxDynamicSharedMemorySize, convSmem);
    cudaFuncSetAttribute(highway_mma_kernel, cudaFuncAttributeMaxDynamicSharedMemorySize, hwSmem);

    int convGrid = (N + 255) / 256;
    int hwGrid   = (N + 127) / 128;
    int scanBlocks = (SEGS + 1023) / 1024;
    int n2 = N * 32;
    int initGrid = (n2 > SEGS ? n2 : SEGS);
    initGrid = (initGrid + 255) / 256;

    // ---- fused init + CSR build (graph identical in both layers) ----
    init_kernel<<<initGrid, 256>>>(x, xbp, n2);
    hist_kernel<<<(E + 255) / 256, 256>>>(dst, rel, E);
    scan_lb_kernel<<<scanBlocks, 1024>>>(SEGS);
    scatter_kernel<<<(E + 255) / 256, 256>>>(src, dst, rel, E);

    int aggGrid = SEGS / 32;   // 8 lanes per segment

    // ---- layer 1 ----
    aggregate_kernel<<<aggGrid, 256>>>(xbp);
    conv_mma_kernel<<<convGrid, 256, convSmem>>>(xbp, Sp, c1w, c1b, c1ws, c1bs, h1p, N);
    highway_mma_kernel<<<hwGrid, 256, hwSmem>>>(h1p, x, h1pw, h1pb, h1tw, h1tb, g1p, g1bp, N);

    // ---- layer 2 ----
    aggregate_kernel<<<aggGrid, 256>>>(g1bp);
    conv_mma_kernel<<<convGrid, 256, convSmem>>>(g1bp, Sp, c2w, c2b, c2ws, c2bs, h2p, N);
    highway_mma_kernel<<<hwGrid, 256, hwSmem>>>(h2p, h1p, h2pw, h2pb, h2tw, h2tb, out, nullptr, N);
}

// round 14
// speedup vs baseline: 1.0527x; 1.0177x over previous
#include <cuda_runtime.h>
#include <cuda_bf16.h>
#include <math.h>

#define Dn   64
#define Rn   4
#define NMAX 100000
#define EMAX 1200000
#define SEGS (NMAX * Rn)
#define BSTR 68    // weight pair-row stride: banks 8q+g -> conflict-free
#define HSTR 68    // h smem stride (floats): row-start banks 4g -> conflict-free quads

// ---------------- scratch ----------------
__device__ int   g_deg[SEGS];
__device__ int   g_off[SEGS + 1];
__device__ int   g_cur[SEGS];
__device__ int   g_srcs[EMAX];
__device__ unsigned long long g_state[512];
__device__ __nv_bfloat162 g_S[(size_t)SEGS * (Dn / 2)];   // per-(node,rel) MEAN, bf16
__device__ __nv_bfloat162 g_xb[(size_t)NMAX * (Dn / 2)];  // bf16 mirror of x
__device__ __nv_bfloat162 g_h1b[(size_t)NMAX * (Dn / 2)]; // bf16 h1 (layer2 prev)
__device__ __nv_bfloat162 g_g1b[(size_t)NMAX * (Dn / 2)]; // bf16 g1 (layer2 features)

__device__ __forceinline__ float sigmoidf_(float v) {
    return 1.0f / (1.0f + __expf(-v));
}

__device__ __forceinline__ float2 b2f2(unsigned u) {
    __nv_bfloat162 t = *reinterpret_cast<__nv_bfloat162*>(&u);
    return __bfloat1622float2(t);
}

__device__ __forceinline__ unsigned packbf(float lo, float hi) {
    __nv_bfloat162 t = __float22bfloat162_rn(make_float2(lo, hi));
    return *reinterpret_cast<unsigned*>(&t);
}

__device__ __forceinline__ void mma_bf16(float d[4], const unsigned a[4], const unsigned b[2]) {
    asm volatile("mma.sync.aligned.m16n8k16.row.col.f32.bf16.bf16.f32 "
                 "{%0,%1,%2,%3}, {%4,%5,%6,%7}, {%8,%9}, {%0,%1,%2,%3};"
                 : "+f"(d[0]), "+f"(d[1]), "+f"(d[2]), "+f"(d[3])
                 : "r"(a[0]), "r"(a[1]), "r"(a[2]), "r"(a[3]), "r"(b[0]), "r"(b[1]));
}

// ---------------- fused init: zero deg/state + fp32->bf16 mirror of x ----------------
__global__ void init_kernel(const float* __restrict__ in, __nv_bfloat162* __restrict__ out, int n2) {
    int i = blockIdx.x * 256 + threadIdx.x;
    if (i < SEGS) g_deg[i] = 0;
    if (i < 512) g_state[i] = 0ULL;
    if (i < n2) {
        float2 v = reinterpret_cast<const float2*>(in)[i];
        out[i] = __float22bfloat162_rn(v);
    }
}

__global__ void hist_kernel(const int* __restrict__ dst, const int* __restrict__ rel, int E) {
    int e = blockIdx.x * blockDim.x + threadIdx.x;
    if (e < E) atomicAdd(&g_deg[dst[e] * Rn + rel[e]], 1);
}

// single-pass exclusive scan, warp-parallel decoupled lookback
__global__ void __launch_bounds__(1024) scan_lb_kernel(int n) {
    __shared__ int wsum[32];
    __shared__ int s_prefix;
    int bid = blockIdx.x;
    int i = bid * 1024 + threadIdx.x;
    int lane = threadIdx.x & 31, wid = threadIdx.x >> 5;
    int v = (i < n) ? g_deg[i] : 0;
    int s = v;
#pragma unroll
    for (int d = 1; d < 32; d <<= 1) {
        int t = __shfl_up_sync(0xffffffffu, s, d);
        if (lane >= d) s += t;
    }
    if (lane == 31) wsum[wid] = s;
    __syncthreads();
    if (wid == 0) {
        int t = wsum[lane];
#pragma unroll
        for (int d = 1; d < 32; d <<= 1) {
            int u = __shfl_up_sync(0xffffffffu, t, d);
            if (lane >= d) t += u;
        }
        wsum[lane] = t;
    }
    __syncthreads();
    int add = (wid > 0) ? wsum[wid - 1] : 0;
    int inc = s + add;
    int agg = wsum[31];

    if (bid == 0) {
        if (threadIdx.x == 0) {
            atomicExch(&g_state[0], (2ULL << 32) | (unsigned)agg);
            s_prefix = 0;
        }
    } else {
        if (threadIdx.x == 0)
            atomicExch(&g_state[bid], (1ULL << 32) | (unsigned)agg);
        if (wid == 0) {
            int run = 0;
            int winEnd = bid;
            bool done = false;
            while (!done) {
                int j = winEnd - 1 - lane;
                unsigned long long st;
                unsigned flag;
                if (j >= 0) {
                    do {
                        st = atomicAdd(&g_state[j], 0ULL);
                        flag = (unsigned)(st >> 32);
                    } while (flag == 0);
                } else {
                    st = 2ULL << 32;
                    flag = 2;
                }
                unsigned pm = __ballot_sync(0xffffffffu, flag == 2);
                int val;
                if (pm) {
                    int firstP = __ffs(pm) - 1;
                    val = (lane <= firstP) ? (int)(unsigned)st : 0;
                    done = true;
                } else {
                    val = (j >= 0) ? (int)(unsigned)st : 0;
                }
#pragma unroll
                for (int d = 16; d; d >>= 1)
                    val += __shfl_down_sync(0xffffffffu, val, d);
                if (lane == 0) run += val;
                winEnd -= 32;
            }
            if (lane == 0) {
                atomicExch(&g_state[bid], (2ULL << 32) | (unsigned)(run + agg));
                s_prefix = run;
            }
        }
    }
    __syncthreads();
    int off = s_prefix + inc - v;
    if (i < n) { g_off[i] = off; g_cur[i] = off; }
    if (i == n - 1) g_off[n] = off + v;
}

__global__ void scatter_kernel(const int* __restrict__ src, const int* __restrict__ dst,
                               const int* __restrict__ rel, int E) {
    int e = blockIdx.x * blockDim.x + threadIdx.x;
    if (e >= E) return;
    int seg = dst[e] * Rn + rel[e];
    int p = atomicAdd(&g_cur[seg], 1);
    g_srcs[p] = src[e];
}

// ---------------- aggregate: S[seg] = MEAN over edges of xb[src] ----------------
__global__ void __launch_bounds__(256) aggregate_kernel(const __nv_bfloat162* __restrict__ xb) {
    int t = blockIdx.x * 256 + threadIdx.x;
    int seg = t >> 3;
    int lane = t & 7;
    if (seg >= SEGS) return;
    const uint4* rows = reinterpret_cast<const uint4*>(xb);
    int e0 = __ldg(&g_off[seg]);
    int e1 = __ldg(&g_off[seg + 1]);
    float a0 = 0.f, a1 = 0.f, a2 = 0.f, a3 = 0.f;
    float a4 = 0.f, a5 = 0.f, a6 = 0.f, a7 = 0.f;
    int e = e0;
    for (; e + 3 < e1; e += 4) {
        int s0 = __ldg(&g_srcs[e]);
        int s1 = __ldg(&g_srcs[e + 1]);
        int s2 = __ldg(&g_srcs[e + 2]);
        int s3 = __ldg(&g_srcs[e + 3]);
        uint4 u0 = __ldg(&rows[(size_t)s0 * 8 + lane]);
        uint4 u1 = __ldg(&rows[(size_t)s1 * 8 + lane]);
        uint4 u2 = __ldg(&rows[(size_t)s2 * 8 + lane]);
        uint4 u3 = __ldg(&rows[(size_t)s3 * 8 + lane]);
        float2 p;
        p = b2f2(u0.x); a0 += p.x; a1 += p.y;
        p = b2f2(u0.y); a2 += p.x; a3 += p.y;
        p = b2f2(u0.z); a4 += p.x; a5 += p.y;
        p = b2f2(u0.w); a6 += p.x; a7 += p.y;
        p = b2f2(u1.x); a0 += p.x; a1 += p.y;
        p = b2f2(u1.y); a2 += p.x; a3 += p.y;
        p = b2f2(u1.z); a4 += p.x; a5 += p.y;
        p = b2f2(u1.w); a6 += p.x; a7 += p.y;
        p = b2f2(u2.x); a0 += p.x; a1 += p.y;
        p = b2f2(u2.y); a2 += p.x; a3 += p.y;
        p = b2f2(u2.z); a4 += p.x; a5 += p.y;
        p = b2f2(u2.w); a6 += p.x; a7 += p.y;
        p = b2f2(u3.x); a0 += p.x; a1 += p.y;
        p = b2f2(u3.y); a2 += p.x; a3 += p.y;
        p = b2f2(u3.z); a4 += p.x; a5 += p.y;
        p = b2f2(u3.w); a6 += p.x; a7 += p.y;
    }
    for (; e < e1; e++) {
        int s0 = __ldg(&g_srcs[e]);
        uint4 u0 = __ldg(&rows[(size_t)s0 * 8 + lane]);
        float2 p;
        p = b2f2(u0.x); a0 += p.x; a1 += p.y;
        p = b2f2(u0.y); a2 += p.x; a3 += p.y;
        p = b2f2(u0.z); a4 += p.x; a5 += p.y;
        p = b2f2(u0.w); a6 += p.x; a7 += p.y;
    }
    int d = e1 - e0;
    float inv = 1.0f / (float)(d > 1 ? d : 1);
    uint4 o;
    o.x = packbf(a0 * inv, a1 * inv);
    o.y = packbf(a2 * inv, a3 * inv);
    o.z = packbf(a4 * inv, a5 * inv);
    o.w = packbf(a6 * inv, a7 * inv);
    reinterpret_cast<uint4*>(g_S)[(size_t)seg * 8 + lane] = o;
}

// ---------------- fused layer: conv mma -> h (smem) -> highway mma + blend ----------------
// 256 threads / 8 warps, 16 nodes per warp -> 128 nodes per block.
__global__ void __launch_bounds__(256)
fused_layer_kernel(const __nv_bfloat162* __restrict__ xb,   // layer features bf16
                   const __nv_bfloat162* __restrict__ S,
                   const float* __restrict__ w,    // [64][256]
                   const float* __restrict__ b,
                   const float* __restrict__ ws,   // [64][64]
                   const float* __restrict__ bs,
                   const __nv_bfloat162* __restrict__ prevb, // highway prev, bf16
                   const float* __restrict__ pw,   // [64][128]
                   const float* __restrict__ pb,
                   const float* __restrict__ tw,   // [64][128]
                   const float* __restrict__ tb,
                   float* __restrict__ outf,                 // fp32 out (or null)
                   __nv_bfloat162* __restrict__ outb,        // bf16 out (or null)
                   __nv_bfloat162* __restrict__ houtb,       // bf16 h out (or null)
                   int N) {
    extern __shared__ unsigned smu[];
    unsigned* swc = smu;                           // 160 * BSTR  (conv weights)
    unsigned* swp = swc + 160 * BSTR;              // 64 * BSTR   (highway p)
    unsigned* swt = swp + 64 * BSTR;               // 64 * BSTR   (highway t)
    float* hs  = (float*)(swt + 64 * BSTR);        // 128 * HSTR  (h, fp32)
    float* sbc = hs + 128 * HSTR;                  // 64
    float* sbp = sbc + Dn;                         // 64
    float* sbt = sbp + Dn;                         // 64
    int tid = threadIdx.x;

    // stage conv weights as bf16x2 pair-rows
    for (int idx = tid; idx < Dn * 128; idx += 256) {
        int j = idx >> 7, kp = idx & 127;
        float2 v = *reinterpret_cast<const float2*>(w + j * 256 + 2 * kp);
        swc[kp * BSTR + j] = packbf(v.x, v.y);
    }
    for (int idx = tid; idx < Dn * 32; idx += 256) {
        int j = idx >> 5, kp = idx & 31;
        float2 v = *reinterpret_cast<const float2*>(ws + j * 64 + 2 * kp);
        swc[(128 + kp) * BSTR + j] = packbf(v.x, v.y);
    }
    // stage highway weights
    for (int idx = tid; idx < Dn * 64; idx += 256) {
        int j = idx >> 6, kp = idx & 63;
        float2 vp = *reinterpret_cast<const float2*>(pw + j * 128 + 2 * kp);
        float2 vt = *reinterpret_cast<const float2*>(tw + j * 128 + 2 * kp);
        swp[kp * BSTR + j] = packbf(vp.x, vp.y);
        swt[kp * BSTR + j] = packbf(vt.x, vt.y);
    }
    if (tid < Dn) {
        sbc[tid] = b[tid] + bs[tid];
        sbp[tid] = pb[tid];
        sbt[tid] = tb[tid];
    }
    __syncthreads();

    int lane = tid & 31, warp = tid >> 5;
    int g = lane >> 2, q = lane & 3;
    int mbase = blockIdx.x * 128 + warp * 16;
    int lw0 = warp * 16 + g, lw1 = lw0 + 8;      // local rows
    int r0 = mbase + g, r1 = r0 + 8;
    int cr0 = min(r0, N - 1), cr1 = min(r1, N - 1);

    // ---- phase A: conv ----
    {
        float acc[8][4];
#pragma unroll
        for (int n = 0; n < 8; n++)
#pragma unroll
            for (int i = 0; i < 4; i++) acc[n][i] = 0.f;

        const uint2* S0 = reinterpret_cast<const uint2*>(S + (size_t)cr0 * 128);
        const uint2* S1 = reinterpret_cast<const uint2*>(S + (size_t)cr1 * 128);
#pragma unroll 2
        for (int kw = 0; kw < 16; kw++) {
            int ui = kw * 4 + q;
            uint2 U0 = S0[ui], U1 = S1[ui];
            unsigned a[4] = { U0.x, U1.x, U0.y, U1.y };
            const unsigned* w0 = swc + (kw * 8 + 2 * q) * BSTR + g;
#pragma unroll
            for (int n = 0; n < 8; n++) {
                unsigned bb[2] = { w0[n * 8], w0[BSTR + n * 8] };
                mma_bf16(acc[n], a, bb);
            }
        }
        const uint2* X0 = reinterpret_cast<const uint2*>(xb + (size_t)cr0 * 32);
        const uint2* X1 = reinterpret_cast<const uint2*>(xb + (size_t)cr1 * 32);
#pragma unroll
        for (int kw = 0; kw < 4; kw++) {
            int ui = kw * 4 + q;
            uint2 U0 = X0[ui], U1 = X1[ui];
            unsigned a[4] = { U0.x, U1.x, U0.y, U1.y };
            const unsigned* w0 = swc + (128 + kw * 8 + 2 * q) * BSTR + g;
#pragma unroll
            for (int n = 0; n < 8; n++) {
                unsigned bb[2] = { w0[n * 8], w0[BSTR + n * 8] };
                mma_bf16(acc[n], a, bb);
            }
        }

#pragma unroll
        for (int n = 0; n < 8; n++) {
            int col = n * 8 + 2 * q;
            float b0v = sbc[col], b1v = sbc[col + 1];
            float2 h0 = { sigmoidf_(acc[n][0] + b0v), sigmoidf_(acc[n][1] + b1v) };
            float2 h1 = { sigmoidf_(acc[n][2] + b0v), sigmoidf_(acc[n][3] + b1v) };
            *reinterpret_cast<float2*>(hs + lw0 * HSTR + col) = h0;
            *reinterpret_cast<float2*>(hs + lw1 * HSTR + col) = h1;
            if (houtb) {
                if (r0 < N) houtb[((size_t)r0 * Dn + col) >> 1] = __float22bfloat162_rn(h0);
                if (r1 < N) houtb[((size_t)r1 * Dn + col) >> 1] = __float22bfloat162_rn(h1);
            }
        }
    }
    __syncthreads();

    // ---- phase B: highway ----
    float accP[8][4], accT[8][4];
#pragma unroll
    for (int n = 0; n < 8; n++)
#pragma unroll
        for (int i = 0; i < 4; i++) { accP[n][i] = 0.f; accT[n][i] = 0.f; }

    const float4* H0 = reinterpret_cast<const float4*>(hs + lw0 * HSTR);
    const float4* H1 = reinterpret_cast<const float4*>(hs + lw1 * HSTR);
    const uint2* P0 = reinterpret_cast<const uint2*>(prevb + (size_t)cr0 * 32);
    const uint2* P1 = reinterpret_cast<const uint2*>(prevb + (size_t)cr1 * 32);

#pragma unroll
    for (int kw = 0; kw < 4; kw++) {
        int ui = kw * 4 + q;
        float4 v0 = H0[ui], v1 = H1[ui];
        unsigned a[4] = { packbf(v0.x, v0.y), packbf(v1.x, v1.y),
                          packbf(v0.z, v0.w), packbf(v1.z, v1.w) };
        const unsigned* p0 = swp + (kw * 8 + 2 * q) * BSTR + g;
        const unsigned* t0 = swt + (kw * 8 + 2 * q) * BSTR + g;
#pragma unroll
        for (int n = 0; n < 8; n++) {
            unsigned bp[2] = { p0[n * 8], p0[BSTR + n * 8] };
            unsigned bt[2] = { t0[n * 8], t0[BSTR + n * 8] };
            mma_bf16(accP[n], a, bp);
            mma_bf16(accT[n], a, bt);
        }
    }
#pragma unroll
    for (int kw = 0; kw < 4; kw++) {
        int ui = kw * 4 + q;
        uint2 U0 = P0[ui], U1 = P1[ui];
        unsigned a[4] = { U0.x, U1.x, U0.y, U1.y };
        const unsigned* p0 = swp + (32 + kw * 8 + 2 * q) * BSTR + g;
        const unsigned* t0 = swt + (32 + kw * 8 + 2 * q) * BSTR + g;
#pragma unroll
        for (int n = 0; n < 8; n++) {
            unsigned bp[2] = { p0[n * 8], p0[BSTR + n * 8] };
            unsigned bt[2] = { t0[n * 8], t0[BSTR + n * 8] };
            mma_bf16(accP[n], a, bp);
            mma_bf16(accT[n], a, bt);
        }
    }

#pragma unroll
    for (int n = 0; n < 8; n++) {
        int col = n * 8 + 2 * q;
        float bp0 = sbp[col], bp1 = sbp[col + 1];
        float bt0 = sbt[col], bt1 = sbt[col + 1];
        {
            float2 hv = *reinterpret_cast<const float2*>(hs + lw0 * HSTR + col);
            float pr0 = fmaxf(accP[n][0] + bp0, 0.f);
            float pr1 = fmaxf(accP[n][1] + bp1, 0.f);
            float g0 = sigmoidf_(accT[n][0] + bt0);
            float g1 = sigmoidf_(accT[n][1] + bt1);
            float2 o = { g0 * pr0 + (1.f - g0) * hv.x, g1 * pr1 + (1.f - g1) * hv.y };
            if (r0 < N) {
                if (outf) *reinterpret_cast<float2*>(outf + (size_t)r0 * Dn + col) = o;
                if (outb) outb[((size_t)r0 * Dn + col) >> 1] = __float22bfloat162_rn(o);
            }
        }
        {
            float2 hv = *reinterpret_cast<const float2*>(hs + lw1 * HSTR + col);
            float pr0 = fmaxf(accP[n][2] + bp0, 0.f);
            float pr1 = fmaxf(accP[n][3] + bp1, 0.f);
            float g0 = sigmoidf_(accT[n][2] + bt0);
            float g1 = sigmoidf_(accT[n][3] + bt1);
            float2 o = { g0 * pr0 + (1.f - g0) * hv.x, g1 * pr1 + (1.f - g1) * hv.y };
            if (r1 < N) {
                if (outf) *reinterpret_cast<float2*>(outf + (size_t)r1 * Dn + col) = o;
                if (outb) outb[((size_t)r1 * Dn + col) >> 1] = __float22bfloat162_rn(o);
            }
        }
    }
}

// ---------------- launch ----------------
extern "C" void kernel_launch(void* const* d_in, const int* in_sizes, int n_in,
                              void* d_out, int out_size) {
    const float* x    = (const float*)d_in[0];
    const int*   src  = (const int*)d_in[1];
    const int*   dst  = (const int*)d_in[2];
    const int*   rel  = (const int*)d_in[3];
    const float* c1w  = (const float*)d_in[4];
    const float* c1b  = (const float*)d_in[5];
    const float* c1ws = (const float*)d_in[6];
    const float* c1bs = (const float*)d_in[7];
    const float* h1pw = (const float*)d_in[8];
    const float* h1pb = (const float*)d_in[9];
    const float* h1tw = (const float*)d_in[10];
    const float* h1tb = (const float*)d_in[11];
    const float* c2w  = (const float*)d_in[12];
    const float* c2b  = (const float*)d_in[13];
    const float* c2ws = (const float*)d_in[14];
    const float* c2bs = (const float*)d_in[15];
    const float* h2pw = (const float*)d_in[16];
    const float* h2pb = (const float*)d_in[17];
    const float* h2tw = (const float*)d_in[18];
    const float* h2tb = (const float*)d_in[19];
    float* out = (float*)d_out;

    int N = in_sizes[0] / Dn;
    int E = in_sizes[1];

    __nv_bfloat162 *Sp, *xbp, *h1bp, *g1bp;
    cudaGetSymbolAddress((void**)&Sp, g_S);
    cudaGetSymbolAddress((void**)&xbp, g_xb);
    cudaGetSymbolAddress((void**)&h1bp, g_h1b);
    cudaGetSymbolAddress((void**)&g1bp, g_g1b);

    const int fusedSmem = (160 * BSTR + 64 * BSTR + 64 * BSTR) * 4   // weights
                        + 128 * HSTR * 4                              // h
                        + 192 * 4;                                    // biases
    cudaFuncSetAttribute(fused_layer_kernel, cudaFuncAttributeMaxDynamicSharedMemorySize, fusedSmem);

    int fusedGrid = (N + 127) / 128;
    int scanBlocks = (SEGS + 1023) / 1024;
    int n2 = N * 32;
    int initGrid = (n2 > SEGS ? n2 : SEGS);
    initGrid = (initGrid + 255) / 256;

    // ---- fused init + CSR build (graph identical in both layers) ----
    init_kernel<<<initGrid, 256>>>(x, xbp, n2);
    hist_kernel<<<(E + 255) / 256, 256>>>(dst, rel, E);
    scan_lb_kernel<<<scanBlocks, 1024>>>(SEGS);
    scatter_kernel<<<(E + 255) / 256, 256>>>(src, dst, rel, E);

    int aggGrid = SEGS / 32;   // 8 lanes per segment

    // ---- layer 1: conv+highway fused; prev = x (via xb mirror) ----
    aggregate_kernel<<<aggGrid, 256>>>(xbp);
    fused_layer_kernel<<<fusedGrid, 256, fusedSmem>>>(
        xbp, Sp, c1w, c1b, c1ws, c1bs,
        xbp, h1pw, h1pb, h1tw, h1tb,
        nullptr, g1bp, h1bp, N);

    // ---- layer 2: prev = h1 (bf16 mirror) ----
    aggregate_kernel<<<aggGrid, 256>>>(g1bp);
    fused_layer_kernel<<<fusedGrid, 256, fusedSmem>>>(
        g1bp, Sp, c2w, c2b, c2ws, c2bs,
        h1bp, h2pw, h2pb, h2tw, h2tb,
        out, nullptr, nullptr, N);
}

// round 15
// speedup vs baseline: 1.0981x; 1.0431x over previous
#include <cuda_runtime.h>
#include <cuda_bf16.h>
#include <math.h>

#define Dn   64
#define Rn   4
#define NMAX 100000
#define EMAX 1200000
#define SEGS (NMAX * Rn)
#define SU2  68    // uint2 weight stride: bank-pair (4q+g)%16 -> conflict-free LDS.64
#define HSTR 68    // h smem stride (floats)

// ---------------- scratch ----------------
__device__ int   g_deg[SEGS];
__device__ int   g_off[SEGS + 1];
__device__ int   g_cur[SEGS];
__device__ int   g_srcs[EMAX];
__device__ unsigned long long g_state[512];
__device__ __nv_bfloat162 g_S[(size_t)SEGS * (Dn / 2)];   // per-(node,rel) MEAN, bf16
__device__ __nv_bfloat162 g_xb[(size_t)NMAX * (Dn / 2)];  // bf16 mirror of x
__device__ __nv_bfloat162 g_h1b[(size_t)NMAX * (Dn / 2)]; // bf16 h1 (layer2 prev)
__device__ __nv_bfloat162 g_g1b[(size_t)NMAX * (Dn / 2)]; // bf16 g1 (layer2 features)

__device__ __forceinline__ float sigmoidf_(float v) {
    return 1.0f / (1.0f + __expf(-v));
}

__device__ __forceinline__ float2 b2f2(unsigned u) {
    __nv_bfloat162 t = *reinterpret_cast<__nv_bfloat162*>(&u);
    return __bfloat1622float2(t);
}

__device__ __forceinline__ unsigned packbf(float lo, float hi) {
    __nv_bfloat162 t = __float22bfloat162_rn(make_float2(lo, hi));
    return *reinterpret_cast<unsigned*>(&t);
}

__device__ __forceinline__ uint2 pack4(float4 v) {
    return make_uint2(packbf(v.x, v.y), packbf(v.z, v.w));
}

__device__ __forceinline__ void mma_bf16(float d[4], const unsigned a[4], const unsigned b[2]) {
    asm volatile("mma.sync.aligned.m16n8k16.row.col.f32.bf16.bf16.f32 "
                 "{%0,%1,%2,%3}, {%4,%5,%6,%7}, {%8,%9}, {%0,%1,%2,%3};"
                 : "+f"(d[0]), "+f"(d[1]), "+f"(d[2]), "+f"(d[3])
                 : "r"(a[0]), "r"(a[1]), "r"(a[2]), "r"(a[3]), "r"(b[0]), "r"(b[1]));
}

// ---------------- fused init: zero deg/state + fp32->bf16 mirror of x ----------------
__global__ void init_kernel(const float* __restrict__ in, __nv_bfloat162* __restrict__ out, int n2) {
    int i = blockIdx.x * 256 + threadIdx.x;
    if (i < SEGS) g_deg[i] = 0;
    if (i < 512) g_state[i] = 0ULL;
    if (i < n2) {
        float2 v = reinterpret_cast<const float2*>(in)[i];
        out[i] = __float22bfloat162_rn(v);
    }
}

__global__ void hist_kernel(const int* __restrict__ dst, const int* __restrict__ rel, int E) {
    int e = blockIdx.x * blockDim.x + threadIdx.x;
    if (e < E) atomicAdd(&g_deg[dst[e] * Rn + rel[e]], 1);
}

// single-pass exclusive scan, warp-parallel decoupled lookback
__global__ void __launch_bounds__(1024) scan_lb_kernel(int n) {
    __shared__ int wsum[32];
    __shared__ int s_prefix;
    int bid = blockIdx.x;
    int i = bid * 1024 + threadIdx.x;
    int lane = threadIdx.x & 31, wid = threadIdx.x >> 5;
    int v = (i < n) ? g_deg[i] : 0;
    int s = v;
#pragma unroll
    for (int d = 1; d < 32; d <<= 1) {
        int t = __shfl_up_sync(0xffffffffu, s, d);
        if (lane >= d) s += t;
    }
    if (lane == 31) wsum[wid] = s;
    __syncthreads();
    if (wid == 0) {
        int t = wsum[lane];
#pragma unroll
        for (int d = 1; d < 32; d <<= 1) {
            int u = __shfl_up_sync(0xffffffffu, t, d);
            if (lane >= d) t += u;
        }
        wsum[lane] = t;
    }
    __syncthreads();
    int add = (wid > 0) ? wsum[wid - 1] : 0;
    int inc = s + add;
    int agg = wsum[31];

    if (bid == 0) {
        if (threadIdx.x == 0) {
            atomicExch(&g_state[0], (2ULL << 32) | (unsigned)agg);
            s_prefix = 0;
        }
    } else {
        if (threadIdx.x == 0)
            atomicExch(&g_state[bid], (1ULL << 32) | (unsigned)agg);
        if (wid == 0) {
            int run = 0;
            int winEnd = bid;
            bool done = false;
            while (!done) {
                int j = winEnd - 1 - lane;
                unsigned long long st;
                unsigned flag;
                if (j >= 0) {
                    do {
                        st = atomicAdd(&g_state[j], 0ULL);
                        flag = (unsigned)(st >> 32);
                    } while (flag == 0);
                } else {
                    st = 2ULL << 32;
                    flag = 2;
                }
                unsigned pm = __ballot_sync(0xffffffffu, flag == 2);
                int val;
                if (pm) {
                    int firstP = __ffs(pm) - 1;
                    val = (lane <= firstP) ? (int)(unsigned)st : 0;
                    done = true;
                } else {
                    val = (j >= 0) ? (int)(unsigned)st : 0;
                }
#pragma unroll
                for (int d = 16; d; d >>= 1)
                    val += __shfl_down_sync(0xffffffffu, val, d);
                if (lane == 0) run += val;
                winEnd -= 32;
            }
            if (lane == 0) {
                atomicExch(&g_state[bid], (2ULL << 32) | (unsigned)(run + agg));
                s_prefix = run;
            }
        }
    }
    __syncthreads();
    int off = s_prefix + inc - v;
    if (i < n) { g_off[i] = off; g_cur[i] = off; }
    if (i == n - 1) g_off[n] = off + v;
}

__global__ void scatter_kernel(const int* __restrict__ src, const int* __restrict__ dst,
                               const int* __restrict__ rel, int E) {
    int e = blockIdx.x * blockDim.x + threadIdx.x;
    if (e >= E) return;
    int seg = dst[e] * Rn + rel[e];
    int p = atomicAdd(&g_cur[seg], 1);
    g_srcs[p] = src[e];
}

// ---------------- aggregate: S[seg] = MEAN over edges of xb[src] ----------------
__global__ void __launch_bounds__(256) aggregate_kernel(const __nv_bfloat162* __restrict__ xb) {
    int t = blockIdx.x * 256 + threadIdx.x;
    int seg = t >> 3;
    int lane = t & 7;
    if (seg >= SEGS) return;
    const uint4* rows = reinterpret_cast<const uint4*>(xb);
    int e0 = __ldg(&g_off[seg]);
    int e1 = __ldg(&g_off[seg + 1]);
    float a0 = 0.f, a1 = 0.f, a2 = 0.f, a3 = 0.f;
    float a4 = 0.f, a5 = 0.f, a6 = 0.f, a7 = 0.f;
    int e = e0;
    for (; e + 3 < e1; e += 4) {
        int s0 = __ldg(&g_srcs[e]);
        int s1 = __ldg(&g_srcs[e + 1]);
        int s2 = __ldg(&g_srcs[e + 2]);
        int s3 = __ldg(&g_srcs[e + 3]);
        uint4 u0 = __ldg(&rows[(size_t)s0 * 8 + lane]);
        uint4 u1 = __ldg(&rows[(size_t)s1 * 8 + lane]);
        uint4 u2 = __ldg(&rows[(size_t)s2 * 8 + lane]);
        uint4 u3 = __ldg(&rows[(size_t)s3 * 8 + lane]);
        float2 p;
        p = b2f2(u0.x); a0 += p.x; a1 += p.y;
        p = b2f2(u0.y); a2 += p.x; a3 += p.y;
        p = b2f2(u0.z); a4 += p.x; a5 += p.y;
        p = b2f2(u0.w); a6 += p.x; a7 += p.y;
        p = b2f2(u1.x); a0 += p.x; a1 += p.y;
        p = b2f2(u1.y); a2 += p.x; a3 += p.y;
        p = b2f2(u1.z); a4 += p.x; a5 += p.y;
        p = b2f2(u1.w); a6 += p.x; a7 += p.y;
        p = b2f2(u2.x); a0 += p.x; a1 += p.y;
        p = b2f2(u2.y); a2 += p.x; a3 += p.y;
        p = b2f2(u2.z); a4 += p.x; a5 += p.y;
        p = b2f2(u2.w); a6 += p.x; a7 += p.y;
        p = b2f2(u3.x); a0 += p.x; a1 += p.y;
        p = b2f2(u3.y); a2 += p.x; a3 += p.y;
        p = b2f2(u3.z); a4 += p.x; a5 += p.y;
        p = b2f2(u3.w); a6 += p.x; a7 += p.y;
    }
    for (; e < e1; e++) {
        int s0 = __ldg(&g_srcs[e]);
        uint4 u0 = __ldg(&rows[(size_t)s0 * 8 + lane]);
        float2 p;
        p = b2f2(u0.x); a0 += p.x; a1 += p.y;
        p = b2f2(u0.y); a2 += p.x; a3 += p.y;
        p = b2f2(u0.z); a4 += p.x; a5 += p.y;
        p = b2f2(u0.w); a6 += p.x; a7 += p.y;
    }
    int d = e1 - e0;
    float inv = 1.0f / (float)(d > 1 ? d : 1);
    uint4 o;
    o.x = packbf(a0 * inv, a1 * inv);
    o.y = packbf(a2 * inv, a3 * inv);
    o.z = packbf(a4 * inv, a5 * inv);
    o.w = packbf(a6 * inv, a7 * inv);
    reinterpret_cast<uint4*>(g_S)[(size_t)seg * 8 + lane] = o;
}

// ---------------- fused layer: conv mma -> h (smem) -> highway mma + blend ----------------
// 256 threads / 8 warps, 16 nodes per warp -> 128 nodes per block.
// Weights stored as uint2 (two consecutive bf16x2 pair-rows) -> B frag = one LDS.64.
__global__ void __launch_bounds__(256)
fused_layer_kernel(const __nv_bfloat162* __restrict__ xb,
                   const __nv_bfloat162* __restrict__ S,
                   const float* __restrict__ w,    // [64][256]
                   const float* __restrict__ b,
                   const float* __restrict__ ws,   // [64][64]
                   const float* __restrict__ bs,
                   const __nv_bfloat162* __restrict__ prevb,
                   const float* __restrict__ pw,   // [64][128]
                   const float* __restrict__ pb,
                   const float* __restrict__ tw,   // [64][128]
                   const float* __restrict__ tb,
                   float* __restrict__ outf,
                   __nv_bfloat162* __restrict__ outb,
                   __nv_bfloat162* __restrict__ houtb,
                   int N) {
    extern __shared__ uint2 smu2[];
    uint2* swc = smu2;                     // 80 * SU2  (conv: k2 = 0..79)
    uint2* swp = swc + 80 * SU2;           // 32 * SU2  (highway p)
    uint2* swt = swp + 32 * SU2;           // 32 * SU2  (highway t)
    float* hs  = (float*)(swt + 32 * SU2); // 128 * HSTR (h, fp32)
    float* sbc = hs + 128 * HSTR;          // 64
    float* sbp = sbc + Dn;                 // 64
    float* sbt = sbp + Dn;                 // 64
    int tid = threadIdx.x;

    // stage conv weights: k2 row holds k {4k2 .. 4k2+3}
    for (int idx = tid; idx < Dn * 64; idx += 256) {       // w: 64 k2-rows
        int j = idx >> 6, k2 = idx & 63;
        float4 v = *reinterpret_cast<const float4*>(w + j * 256 + 4 * k2);
        swc[k2 * SU2 + j] = pack4(v);
    }
    for (int idx = tid; idx < Dn * 16; idx += 256) {       // ws: 16 k2-rows
        int j = idx >> 4, k2 = idx & 15;
        float4 v = *reinterpret_cast<const float4*>(ws + j * 64 + 4 * k2);
        swc[(64 + k2) * SU2 + j] = pack4(v);
    }
    for (int idx = tid; idx < Dn * 32; idx += 256) {       // pw/tw: 32 k2-rows each
        int j = idx >> 5, k2 = idx & 31;
        float4 vp = *reinterpret_cast<const float4*>(pw + j * 128 + 4 * k2);
        float4 vt = *reinterpret_cast<const float4*>(tw + j * 128 + 4 * k2);
        swp[k2 * SU2 + j] = pack4(vp);
        swt[k2 * SU2 + j] = pack4(vt);
    }
    if (tid < Dn) {
        sbc[tid] = b[tid] + bs[tid];
        sbp[tid] = pb[tid];
        sbt[tid] = tb[tid];
    }
    __syncthreads();

    int lane = tid & 31, warp = tid >> 5;
    int g = lane >> 2, q = lane & 3;
    int mbase = blockIdx.x * 128 + warp * 16;
    int lw0 = warp * 16 + g, lw1 = lw0 + 8;
    int r0 = mbase + g, r1 = r0 + 8;
    int cr0 = min(r0, N - 1), cr1 = min(r1, N - 1);

    // ---- phase A: conv ----
    {
        float acc[8][4];
#pragma unroll
        for (int n = 0; n < 8; n++)
#pragma unroll
            for (int i = 0; i < 4; i++) acc[n][i] = 0.f;

        const uint2* S0 = reinterpret_cast<const uint2*>(S + (size_t)cr0 * 128);
        const uint2* S1 = reinterpret_cast<const uint2*>(S + (size_t)cr1 * 128);
#pragma unroll 2
        for (int kw = 0; kw < 16; kw++) {
            int ui = kw * 4 + q;
            uint2 U0 = S0[ui], U1 = S1[ui];
            unsigned a[4] = { U0.x, U1.x, U0.y, U1.y };
            const uint2* wB = swc + (kw * 4 + q) * SU2 + g;
#pragma unroll
            for (int n = 0; n < 8; n++) {
                uint2 bb2 = wB[n * 8];
                unsigned bb[2] = { bb2.x, bb2.y };
                mma_bf16(acc[n], a, bb);
            }
        }
        const uint2* X0 = reinterpret_cast<const uint2*>(xb + (size_t)cr0 * 32);
        const uint2* X1 = reinterpret_cast<const uint2*>(xb + (size_t)cr1 * 32);
#pragma unroll
        for (int kx = 0; kx < 4; kx++) {
            int ui = kx * 4 + q;
            uint2 U0 = X0[ui], U1 = X1[ui];
            unsigned a[4] = { U0.x, U1.x, U0.y, U1.y };
            const uint2* wB = swc + (64 + kx * 4 + q) * SU2 + g;
#pragma unroll
            for (int n = 0; n < 8; n++) {
                uint2 bb2 = wB[n * 8];
                unsigned bb[2] = { bb2.x, bb2.y };
                mma_bf16(acc[n], a, bb);
            }
        }

#pragma unroll
        for (int n = 0; n < 8; n++) {
            int col = n * 8 + 2 * q;
            float b0v = sbc[col], b1v = sbc[col + 1];
            float2 h0 = { sigmoidf_(acc[n][0] + b0v), sigmoidf_(acc[n][1] + b1v) };
            float2 h1 = { sigmoidf_(acc[n][2] + b0v), sigmoidf_(acc[n][3] + b1v) };
            *reinterpret_cast<float2*>(hs + lw0 * HSTR + col) = h0;
            *reinterpret_cast<float2*>(hs + lw1 * HSTR + col) = h1;
            if (houtb) {
                if (r0 < N) houtb[((size_t)r0 * Dn + col) >> 1] = __float22bfloat162_rn(h0);
                if (r1 < N) houtb[((size_t)r1 * Dn + col) >> 1] = __float22bfloat162_rn(h1);
            }
        }
    }
    __syncthreads();

    // ---- phase B: highway ----
    float accP[8][4], accT[8][4];
#pragma unroll
    for (int n = 0; n < 8; n++)
#pragma unroll
        for (int i = 0; i < 4; i++) { accP[n][i] = 0.f; accT[n][i] = 0.f; }

    const float4* H0 = reinterpret_cast<const float4*>(hs + lw0 * HSTR);
    const float4* H1 = reinterpret_cast<const float4*>(hs + lw1 * HSTR);
    const uint2* P0 = reinterpret_cast<const uint2*>(prevb + (size_t)cr0 * 32);
    const uint2* P1 = reinterpret_cast<const uint2*>(prevb + (size_t)cr1 * 32);

#pragma unroll
    for (int kw = 0; kw < 4; kw++) {
        int ui = kw * 4 + q;
        float4 v0 = H0[ui], v1 = H1[ui];
        unsigned a[4] = { packbf(v0.x, v0.y), packbf(v1.x, v1.y),
                          packbf(v0.z, v0.w), packbf(v1.z, v1.w) };
        const uint2* pB = swp + (kw * 4 + q) * SU2 + g;
        const uint2* tB = swt + (kw * 4 + q) * SU2 + g;
#pragma unroll
        for (int n = 0; n < 8; n++) {
            uint2 bp2 = pB[n * 8], bt2 = tB[n * 8];
            unsigned bp[2] = { bp2.x, bp2.y };
            unsigned bt[2] = { bt2.x, bt2.y };
            mma_bf16(accP[n], a, bp);
            mma_bf16(accT[n], a, bt);
        }
    }
#pragma unroll
    for (int kw = 0; kw < 4; kw++) {
        int ui = kw * 4 + q;
        uint2 U0 = P0[ui], U1 = P1[ui];
        unsigned a[4] = { U0.x, U1.x, U0.y, U1.y };
        const uint2* pB = swp + (16 + kw * 4 + q) * SU2 + g;
        const uint2* tB = swt + (16 + kw * 4 + q) * SU2 + g;
#pragma unroll
        for (int n = 0; n < 8; n++) {
            uint2 bp2 = pB[n * 8], bt2 = tB[n * 8];
            unsigned bp[2] = { bp2.x, bp2.y };
            unsigned bt[2] = { bt2.x, bt2.y };
            mma_bf16(accP[n], a, bp);
            mma_bf16(accT[n], a, bt);
        }
    }

#pragma unroll
    for (int n = 0; n < 8; n++) {
        int col = n * 8 + 2 * q;
        float bp0 = sbp[col], bp1 = sbp[col + 1];
        float bt0 = sbt[col], bt1 = sbt[col + 1];
        {
            float2 hv = *reinterpret_cast<const float2*>(hs + lw0 * HSTR + col);
            float pr0 = fmaxf(accP[n][0] + bp0, 0.f);
            float pr1 = fmaxf(accP[n][1] + bp1, 0.f);
            float g0 = sigmoidf_(accT[n][0] + bt0);
            float g1 = sigmoidf_(accT[n][1] + bt1);
            float2 o = { g0 * pr0 + (1.f - g0) * hv.x, g1 * pr1 + (1.f - g1) * hv.y };
            if (r0 < N) {
                if (outf) *reinterpret_cast<float2*>(outf + (size_t)r0 * Dn + col) = o;
                if (outb) outb[((size_t)r0 * Dn + col) >> 1] = __float22bfloat162_rn(o);
            }
        }
        {
            float2 hv = *reinterpret_cast<const float2*>(hs + lw1 * HSTR + col);
            float pr0 = fmaxf(accP[n][2] + bp0, 0.f);
            float pr1 = fmaxf(accP[n][3] + bp1, 0.f);
            float g0 = sigmoidf_(accT[n][2] + bt0);
            float g1 = sigmoidf_(accT[n][3] + bt1);
            float2 o = { g0 * pr0 + (1.f - g0) * hv.x, g1 * pr1 + (1.f - g1) * hv.y };
            if (r1 < N) {
                if (outf) *reinterpret_cast<float2*>(outf + (size_t)r1 * Dn + col) = o;
                if (outb) outb[((size_t)r1 * Dn + col) >> 1] = __float22bfloat162_rn(o);
            }
        }
    }
}

// ---------------- launch ----------------
extern "C" void kernel_launch(void* const* d_in, const int* in_sizes, int n_in,
                              void* d_out, int out_size) {
    const float* x    = (const float*)d_in[0];
    const int*   src  = (const int*)d_in[1];
    const int*   dst  = (const int*)d_in[2];
    const int*   rel  = (const int*)d_in[3];
    const float* c1w  = (const float*)d_in[4];
    const float* c1b  = (const float*)d_in[5];
    const float* c1ws = (const float*)d_in[6];
    const float* c1bs = (const float*)d_in[7];
    const float* h1pw = (const float*)d_in[8];
    const float* h1pb = (const float*)d_in[9];
    const float* h1tw = (const float*)d_in[10];
    const float* h1tb = (const float*)d_in[11];
    const float* c2w  = (const float*)d_in[12];
    const float* c2b  = (const float*)d_in[13];
    const float* c2ws = (const float*)d_in[14];
    const float* c2bs = (const float*)d_in[15];
    const float* h2pw = (const float*)d_in[16];
    const float* h2pb = (const float*)d_in[17];
    const float* h2tw = (const float*)d_in[18];
    const float* h2tb = (const float*)d_in[19];
    float* out = (float*)d_out;

    int N = in_sizes[0] / Dn;
    int E = in_sizes[1];

    __nv_bfloat162 *Sp, *xbp, *h1bp, *g1bp;
    cudaGetSymbolAddress((void**)&Sp, g_S);
    cudaGetSymbolAddress((void**)&xbp, g_xb);
    cudaGetSymbolAddress((void**)&h1bp, g_h1b);
    cudaGetSymbolAddress((void**)&g1bp, g_g1b);

    const int fusedSmem = (80 + 32 + 32) * SU2 * 8    // weights (uint2)
                        + 128 * HSTR * 4              // h
                        + 192 * 4;                    // biases
    cudaFuncSetAttribute(fused_layer_kernel, cudaFuncAttributeMaxDynamicSharedMemorySize, fusedSmem);

    int fusedGrid = (N + 127) / 128;
    int scanBlocks = (SEGS + 1023) / 1024;
    int n2 = N * 32;
    int initGrid = (n2 > SEGS ? n2 : SEGS);
    initGrid = (initGrid + 255) / 256;

    // ---- fused init + CSR build (graph identical in both layers) ----
    init_kernel<<<initGrid, 256>>>(x, xbp, n2);
    hist_kernel<<<(E + 255) / 256, 256>>>(dst, rel, E);
    scan_lb_kernel<<<scanBlocks, 1024>>>(SEGS);
    scatter_kernel<<<(E + 255) / 256, 256>>>(src, dst, rel, E);

    int aggGrid = SEGS / 32;

    // ---- layer 1 ----
    aggregate_kernel<<<aggGrid, 256>>>(xbp);
    fused_layer_kernel<<<fusedGrid, 256, fusedSmem>>>(
        xbp, Sp, c1w, c1b, c1ws, c1bs,
        xbp, h1pw, h1pb, h1tw, h1tb,
        nullptr, g1bp, h1bp, N);

    // ---- layer 2 ----
    aggregate_kernel<<<aggGrid, 256>>>(g1bp);
    fused_layer_kernel<<<fusedGrid, 256, fusedSmem>>>(
        g1bp, Sp, c2w, c2b, c2ws, c2bs,
        h1bp, h2pw, h2pb, h2tw, h2tb,
        out, nullptr, nullptr, N);
}

// round 16
// speedup vs baseline: 1.1104x; 1.0112x over previous
#include <cuda_runtime.h>
#include <cuda_bf16.h>
#include <math.h>

#define Dn   64
#define Rn   4
#define NMAX 100000
#define EMAX 1200000
#define SEGS (NMAX * Rn)
#define SU2  68    // uint2 weight stride: bank-pair (4q+g)%16 -> conflict-free LDS.64
#define HS2  40    // h bf16 smem stride in unsigneds (160B/row): conflict-free ld/st

// ---------------- scratch ----------------
__device__ int   g_deg[SEGS];
__device__ int   g_off[SEGS + 1];
__device__ int   g_cur[SEGS];
__device__ int   g_srcs[EMAX];
__device__ unsigned long long g_state[512];
__device__ __nv_bfloat162 g_S[(size_t)SEGS * (Dn / 2)];   // per-(node,rel) MEAN, bf16
__device__ __nv_bfloat162 g_xb[(size_t)NMAX * (Dn / 2)];  // bf16 mirror of x
__device__ __nv_bfloat162 g_h1b[(size_t)NMAX * (Dn / 2)]; // bf16 h1 (layer2 prev)
__device__ __nv_bfloat162 g_g1b[(size_t)NMAX * (Dn / 2)]; // bf16 g1 (layer2 features)

__device__ __forceinline__ float sigmoidf_(float v) {
    return 1.0f / (1.0f + __expf(-v));
}

__device__ __forceinline__ float2 b2f2(unsigned u) {
    __nv_bfloat162 t = *reinterpret_cast<__nv_bfloat162*>(&u);
    return __bfloat1622float2(t);
}

__device__ __forceinline__ unsigned packbf(float lo, float hi) {
    __nv_bfloat162 t = __float22bfloat162_rn(make_float2(lo, hi));
    return *reinterpret_cast<unsigned*>(&t);
}

__device__ __forceinline__ uint2 pack4(float4 v) {
    return make_uint2(packbf(v.x, v.y), packbf(v.z, v.w));
}

__device__ __forceinline__ void mma_bf16(float d[4], const unsigned a[4], const unsigned b[2]) {
    asm volatile("mma.sync.aligned.m16n8k16.row.col.f32.bf16.bf16.f32 "
                 "{%0,%1,%2,%3}, {%4,%5,%6,%7}, {%8,%9}, {%0,%1,%2,%3};"
                 : "+f"(d[0]), "+f"(d[1]), "+f"(d[2]), "+f"(d[3])
                 : "r"(a[0]), "r"(a[1]), "r"(a[2]), "r"(a[3]), "r"(b[0]), "r"(b[1]));
}

// ---------------- fused init: zero deg/state + fp32->bf16 mirror of x ----------------
__global__ void init_kernel(const float* __restrict__ in, __nv_bfloat162* __restrict__ out, int n2) {
    int i = blockIdx.x * 256 + threadIdx.x;
    if (i < SEGS) g_deg[i] = 0;
    if (i < 512) g_state[i] = 0ULL;
    if (i < n2) {
        float2 v = reinterpret_cast<const float2*>(in)[i];
        out[i] = __float22bfloat162_rn(v);
    }
}

__global__ void hist_kernel(const int* __restrict__ dst, const int* __restrict__ rel, int E) {
    int e = blockIdx.x * blockDim.x + threadIdx.x;
    if (e < E) atomicAdd(&g_deg[dst[e] * Rn + rel[e]], 1);
}

// single-pass exclusive scan, warp-parallel decoupled lookback
__global__ void __launch_bounds__(1024) scan_lb_kernel(int n) {
    __shared__ int wsum[32];
    __shared__ int s_prefix;
    int bid = blockIdx.x;
    int i = bid * 1024 + threadIdx.x;
    int lane = threadIdx.x & 31, wid = threadIdx.x >> 5;
    int v = (i < n) ? g_deg[i] : 0;
    int s = v;
#pragma unroll
    for (int d = 1; d < 32; d <<= 1) {
        int t = __shfl_up_sync(0xffffffffu, s, d);
        if (lane >= d) s += t;
    }
    if (lane == 31) wsum[wid] = s;
    __syncthreads();
    if (wid == 0) {
        int t = wsum[lane];
#pragma unroll
        for (int d = 1; d < 32; d <<= 1) {
            int u = __shfl_up_sync(0xffffffffu, t, d);
            if (lane >= d) t += u;
        }
        wsum[lane] = t;
    }
    __syncthreads();
    int add = (wid > 0) ? wsum[wid - 1] : 0;
    int inc = s + add;
    int agg = wsum[31];

    if (bid == 0) {
        if (threadIdx.x == 0) {
            atomicExch(&g_state[0], (2ULL << 32) | (unsigned)agg);
            s_prefix = 0;
        }
    } else {
        if (threadIdx.x == 0)
            atomicExch(&g_state[bid], (1ULL << 32) | (unsigned)agg);
        if (wid == 0) {
            int run = 0;
            int winEnd = bid;
            bool done = false;
            while (!done) {
                int j = winEnd - 1 - lane;
                unsigned long long st;
                unsigned flag;
                if (j >= 0) {
                    do {
                        st = atomicAdd(&g_state[j], 0ULL);
                        flag = (unsigned)(st >> 32);
                    } while (flag == 0);
                } else {
                    st = 2ULL << 32;
                    flag = 2;
                }
                unsigned pm = __ballot_sync(0xffffffffu, flag == 2);
                int val;
                if (pm) {
                    int firstP = __ffs(pm) - 1;
                    val = (lane <= firstP) ? (int)(unsigned)st : 0;
                    done = true;
                } else {
                    val = (j >= 0) ? (int)(unsigned)st : 0;
                }
#pragma unroll
                for (int d = 16; d; d >>= 1)
                    val += __shfl_down_sync(0xffffffffu, val, d);
                if (lane == 0) run += val;
                winEnd -= 32;
            }
            if (lane == 0) {
                atomicExch(&g_state[bid], (2ULL << 32) | (unsigned)(run + agg));
                s_prefix = run;
            }
        }
    }
    __syncthreads();
    int off = s_prefix + inc - v;
    if (i < n) { g_off[i] = off; g_cur[i] = off; }
    if (i == n - 1) g_off[n] = off + v;
}

__global__ void scatter_kernel(const int* __restrict__ src, const int* __restrict__ dst,
                               const int* __restrict__ rel, int E) {
    int e = blockIdx.x * blockDim.x + threadIdx.x;
    if (e >= E) return;
    int seg = dst[e] * Rn + rel[e];
    int p = atomicAdd(&g_cur[seg], 1);
    g_srcs[p] = src[e];
}

// ---------------- aggregate: S[seg] = MEAN over edges of xb[src] ----------------
__global__ void __launch_bounds__(256) aggregate_kernel(const __nv_bfloat162* __restrict__ xb) {
    int t = blockIdx.x * 256 + threadIdx.x;
    int seg = t >> 3;
    int lane = t & 7;
    if (seg >= SEGS) return;
    const uint4* rows = reinterpret_cast<const uint4*>(xb);
    int e0 = __ldg(&g_off[seg]);
    int e1 = __ldg(&g_off[seg + 1]);
    float a0 = 0.f, a1 = 0.f, a2 = 0.f, a3 = 0.f;
    float a4 = 0.f, a5 = 0.f, a6 = 0.f, a7 = 0.f;
    int e = e0;
    for (; e + 3 < e1; e += 4) {
        int s0 = __ldg(&g_srcs[e]);
        int s1 = __ldg(&g_srcs[e + 1]);
        int s2 = __ldg(&g_srcs[e + 2]);
        int s3 = __ldg(&g_srcs[e + 3]);
        uint4 u0 = __ldg(&rows[(size_t)s0 * 8 + lane]);
        uint4 u1 = __ldg(&rows[(size_t)s1 * 8 + lane]);
        uint4 u2 = __ldg(&rows[(size_t)s2 * 8 + lane]);
        uint4 u3 = __ldg(&rows[(size_t)s3 * 8 + lane]);
        float2 p;
        p = b2f2(u0.x); a0 += p.x; a1 += p.y;
        p = b2f2(u0.y); a2 += p.x; a3 += p.y;
        p = b2f2(u0.z); a4 += p.x; a5 += p.y;
        p = b2f2(u0.w); a6 += p.x; a7 += p.y;
        p = b2f2(u1.x); a0 += p.x; a1 += p.y;
        p = b2f2(u1.y); a2 += p.x; a3 += p.y;
        p = b2f2(u1.z); a4 += p.x; a5 += p.y;
        p = b2f2(u1.w); a6 += p.x; a7 += p.y;
        p = b2f2(u2.x); a0 += p.x; a1 += p.y;
        p = b2f2(u2.y); a2 += p.x; a3 += p.y;
        p = b2f2(u2.z); a4 += p.x; a5 += p.y;
        p = b2f2(u2.w); a6 += p.x; a7 += p.y;
        p = b2f2(u3.x); a0 += p.x; a1 += p.y;
        p = b2f2(u3.y); a2 += p.x; a3 += p.y;
        p = b2f2(u3.z); a4 += p.x; a5 += p.y;
        p = b2f2(u3.w); a6 += p.x; a7 += p.y;
    }
    for (; e < e1; e++) {
        int s0 = __ldg(&g_srcs[e]);
        uint4 u0 = __ldg(&rows[(size_t)s0 * 8 + lane]);
        float2 p;
        p = b2f2(u0.x); a0 += p.x; a1 += p.y;
        p = b2f2(u0.y); a2 += p.x; a3 += p.y;
        p = b2f2(u0.z); a4 += p.x; a5 += p.y;
        p = b2f2(u0.w); a6 += p.x; a7 += p.y;
    }
    int d = e1 - e0;
    float inv = 1.0f / (float)(d > 1 ? d : 1);
    uint4 o;
    o.x = packbf(a0 * inv, a1 * inv);
    o.y = packbf(a2 * inv, a3 * inv);
    o.z = packbf(a4 * inv, a5 * inv);
    o.w = packbf(a6 * inv, a7 * inv);
    reinterpret_cast<uint4*>(g_S)[(size_t)seg * 8 + lane] = o;
}

// ---------------- fused layer: conv mma -> h (bf16 smem + fp32 regs) -> highway ----------------
// 256 threads / 8 warps, 16 nodes per warp -> 128 nodes per block, 2 blocks/SM.
__global__ void __launch_bounds__(256, 2)
fused_layer_kernel(const __nv_bfloat162* __restrict__ xb,
                   const __nv_bfloat162* __restrict__ S,
                   const float* __restrict__ w,    // [64][256]
                   const float* __restrict__ b,
                   const float* __restrict__ ws,   // [64][64]
                   const float* __restrict__ bs,
                   const __nv_bfloat162* __restrict__ prevb,
                   const float* __restrict__ pw,   // [64][128]
                   const float* __restrict__ pb,
                   const float* __restrict__ tw,   // [64][128]
                   const float* __restrict__ tb,
                   float* __restrict__ outf,
                   __nv_bfloat162* __restrict__ outb,
                   __nv_bfloat162* __restrict__ houtb,
                   int N) {
    extern __shared__ uint2 smu2[];
    uint2* swc = smu2;                        // 80 * SU2  (conv weights)
    uint2* swp = swc + 80 * SU2;              // 32 * SU2  (highway p)
    uint2* swt = swp + 32 * SU2;              // 32 * SU2  (highway t)
    unsigned* hsu = (unsigned*)(swt + 32 * SU2); // 128 * HS2 (h, bf16x2)
    float* sbc = (float*)(hsu + 128 * HS2);   // 64
    float* sbp = sbc + Dn;                    // 64
    float* sbt = sbp + Dn;                    // 64
    int tid = threadIdx.x;

    for (int idx = tid; idx < Dn * 64; idx += 256) {
        int j = idx >> 6, k2 = idx & 63;
        float4 v = *reinterpret_cast<const float4*>(w + j * 256 + 4 * k2);
        swc[k2 * SU2 + j] = pack4(v);
    }
    for (int idx = tid; idx < Dn * 16; idx += 256) {
        int j = idx >> 4, k2 = idx & 15;
        float4 v = *reinterpret_cast<const float4*>(ws + j * 64 + 4 * k2);
        swc[(64 + k2) * SU2 + j] = pack4(v);
    }
    for (int idx = tid; idx < Dn * 32; idx += 256) {
        int j = idx >> 5, k2 = idx & 31;
        float4 vp = *reinterpret_cast<const float4*>(pw + j * 128 + 4 * k2);
        float4 vt = *reinterpret_cast<const float4*>(tw + j * 128 + 4 * k2);
        swp[k2 * SU2 + j] = pack4(vp);
        swt[k2 * SU2 + j] = pack4(vt);
    }
    if (tid < Dn) {
        sbc[tid] = b[tid] + bs[tid];
        sbp[tid] = pb[tid];
        sbt[tid] = tb[tid];
    }
    __syncthreads();

    int lane = tid & 31, warp = tid >> 5;
    int g = lane >> 2, q = lane & 3;
    int mbase = blockIdx.x * 128 + warp * 16;
    int lw0 = warp * 16 + g, lw1 = lw0 + 8;
    int r0 = mbase + g, r1 = r0 + 8;
    int cr0 = min(r0, N - 1), cr1 = min(r1, N - 1);

    // fp32 h values kept for the blend (same thread owns same (row,col) in both phases)
    float hreg[8][4];

    // ---- phase A: conv ----
    {
        float acc[8][4];
#pragma unroll
        for (int n = 0; n < 8; n++)
#pragma unroll
            for (int i = 0; i < 4; i++) acc[n][i] = 0.f;

        const uint2* S0 = reinterpret_cast<const uint2*>(S + (size_t)cr0 * 128);
        const uint2* S1 = reinterpret_cast<const uint2*>(S + (size_t)cr1 * 128);
#pragma unroll 2
        for (int kw = 0; kw < 16; kw++) {
            int ui = kw * 4 + q;
            uint2 U0 = S0[ui], U1 = S1[ui];
            unsigned a[4] = { U0.x, U1.x, U0.y, U1.y };
            const uint2* wB = swc + (kw * 4 + q) * SU2 + g;
#pragma unroll
            for (int n = 0; n < 8; n++) {
                uint2 bb2 = wB[n * 8];
                unsigned bb[2] = { bb2.x, bb2.y };
                mma_bf16(acc[n], a, bb);
            }
        }
        const uint2* X0 = reinterpret_cast<const uint2*>(xb + (size_t)cr0 * 32);
        const uint2* X1 = reinterpret_cast<const uint2*>(xb + (size_t)cr1 * 32);
#pragma unroll
        for (int kx = 0; kx < 4; kx++) {
            int ui = kx * 4 + q;
            uint2 U0 = X0[ui], U1 = X1[ui];
            unsigned a[4] = { U0.x, U1.x, U0.y, U1.y };
            const uint2* wB = swc + (64 + kx * 4 + q) * SU2 + g;
#pragma unroll
            for (int n = 0; n < 8; n++) {
                uint2 bb2 = wB[n * 8];
                unsigned bb[2] = { bb2.x, bb2.y };
                mma_bf16(acc[n], a, bb);
            }
        }

#pragma unroll
        for (int n = 0; n < 8; n++) {
            int col = n * 8 + 2 * q;
            float b0v = sbc[col], b1v = sbc[col + 1];
            hreg[n][0] = sigmoidf_(acc[n][0] + b0v);
            hreg[n][1] = sigmoidf_(acc[n][1] + b1v);
            hreg[n][2] = sigmoidf_(acc[n][2] + b0v);
            hreg[n][3] = sigmoidf_(acc[n][3] + b1v);
            unsigned p0 = packbf(hreg[n][0], hreg[n][1]);
            unsigned p1 = packbf(hreg[n][2], hreg[n][3]);
            hsu[lw0 * HS2 + n * 4 + q] = p0;
            hsu[lw1 * HS2 + n * 4 + q] = p1;
            if (houtb) {
                __nv_bfloat162 t0 = *reinterpret_cast<__nv_bfloat162*>(&p0);
                __nv_bfloat162 t1 = *reinterpret_cast<__nv_bfloat162*>(&p1);
                if (r0 < N) houtb[((size_t)r0 * Dn + col) >> 1] = t0;
                if (r1 < N) houtb[((size_t)r1 * Dn + col) >> 1] = t1;
            }
        }
    }
    __syncthreads();

    // ---- phase B: highway ----
    float accP[8][4], accT[8][4];
#pragma unroll
    for (int n = 0; n < 8; n++)
#pragma unroll
        for (int i = 0; i < 4; i++) { accP[n][i] = 0.f; accT[n][i] = 0.f; }

    const uint2* P0 = reinterpret_cast<const uint2*>(prevb + (size_t)cr0 * 32);
    const uint2* P1 = reinterpret_cast<const uint2*>(prevb + (size_t)cr1 * 32);

#pragma unroll
    for (int kw = 0; kw < 4; kw++) {
        uint2 A0 = *reinterpret_cast<const uint2*>(hsu + lw0 * HS2 + kw * 8 + 2 * q);
        uint2 A1 = *reinterpret_cast<const uint2*>(hsu + lw1 * HS2 + kw * 8 + 2 * q);
        unsigned a[4] = { A0.x, A1.x, A0.y, A1.y };
        const uint2* pB = swp + (kw * 4 + q) * SU2 + g;
        const uint2* tB = swt + (kw * 4 + q) * SU2 + g;
#pragma unroll
        for (int n = 0; n < 8; n++) {
            uint2 bp2 = pB[n * 8], bt2 = tB[n * 8];
            unsigned bp[2] = { bp2.x, bp2.y };
            unsigned bt[2] = { bt2.x, bt2.y };
            mma_bf16(accP[n], a, bp);
            mma_bf16(accT[n], a, bt);
        }
    }
#pragma unroll
    for (int kw = 0; kw < 4; kw++) {
        int ui = kw * 4 + q;
        uint2 U0 = P0[ui], U1 = P1[ui];
        unsigned a[4] = { U0.x, U1.x, U0.y, U1.y };
        const uint2* pB = swp + (16 + kw * 4 + q) * SU2 + g;
        const uint2* tB = swt + (16 + kw * 4 + q) * SU2 + g;
#pragma unroll
        for (int n = 0; n < 8; n++) {
            uint2 bp2 = pB[n * 8], bt2 = tB[n * 8];
            unsigned bp[2] = { bp2.x, bp2.y };
            unsigned bt[2] = { bt2.x, bt2.y };
            mma_bf16(accP[n], a, bp);
            mma_bf16(accT[n], a, bt);
        }
    }

#pragma unroll
    for (int n = 0; n < 8; n++) {
        int col = n * 8 + 2 * q;
        float bp0 = sbp[col], bp1 = sbp[col + 1];
        float bt0 = sbt[col], bt1 = sbt[col + 1];
        {
            float pr0 = fmaxf(accP[n][0] + bp0, 0.f);
            float pr1 = fmaxf(accP[n][1] + bp1, 0.f);
            float g0 = sigmoidf_(accT[n][0] + bt0);
            float g1 = sigmoidf_(accT[n][1] + bt1);
            float2 o = { g0 * pr0 + (1.f - g0) * hreg[n][0],
                         g1 * pr1 + (1.f - g1) * hreg[n][1] };
            if (r0 < N) {
                if (outf) *reinterpret_cast<float2*>(outf + (size_t)r0 * Dn + col) = o;
                if (outb) outb[((size_t)r0 * Dn + col) >> 1] = __float22bfloat162_rn(o);
            }
        }
        {
            float pr0 = fmaxf(accP[n][2] + bp0, 0.f);
            float pr1 = fmaxf(accP[n][3] + bp1, 0.f);
            float g0 = sigmoidf_(accT[n][2] + bt0);
            float g1 = sigmoidf_(accT[n][3] + bt1);
            float2 o = { g0 * pr0 + (1.f - g0) * hreg[n][2],
                         g1 * pr1 + (1.f - g1) * hreg[n][3] };
            if (r1 < N) {
                if (outf) *reinterpret_cast<float2*>(outf + (size_t)r1 * Dn + col) = o;
                if (outb) outb[((size_t)r1 * Dn + col) >> 1] = __float22bfloat162_rn(o);
            }
        }
    }
}

// ---------------- launch ----------------
extern "C" void kernel_launch(void* const* d_in, const int* in_sizes, int n_in,
                              void* d_out, int out_size) {
    const float* x    = (const float*)d_in[0];
    const int*   src  = (const int*)d_in[1];
    const int*   dst  = (const int*)d_in[2];
    const int*   rel  = (const int*)d_in[3];
    const float* c1w  = (const float*)d_in[4];
    const float* c1b  = (const float*)d_in[5];
    const float* c1ws = (const float*)d_in[6];
    const float* c1bs = (const float*)d_in[7];
    const float* h1pw = (const float*)d_in[8];
    const float* h1pb = (const float*)d_in[9];
    const float* h1tw = (const float*)d_in[10];
    const float* h1tb = (const float*)d_in[11];
    const float* c2w  = (const float*)d_in[12];
    const float* c2b  = (const float*)d_in[13];
    const float* c2ws = (const float*)d_in[14];
    const float* c2bs = (const float*)d_in[15];
    const float* h2pw = (const float*)d_in[16];
    const float* h2pb = (const float*)d_in[17];
    const float* h2tw = (const float*)d_in[18];
    const float* h2tb = (const float*)d_in[19];
    float* out = (float*)d_out;

    int N = in_sizes[0] / Dn;
    int E = in_sizes[1];

    __nv_bfloat162 *Sp, *xbp, *h1bp, *g1bp;
    cudaGetSymbolAddress((void**)&Sp, g_S);
    cudaGetSymbolAddress((void**)&xbp, g_xb);
    cudaGetSymbolAddress((void**)&h1bp, g_h1b);
    cudaGetSymbolAddress((void**)&g1bp, g_g1b);

    const int fusedSmem = (80 + 32 + 32) * SU2 * 8    // weights (uint2)
                        + 128 * HS2 * 4               // h (bf16x2)
                        + 192 * 4;                    // biases
    cudaFuncSetAttribute(fused_layer_kernel, cudaFuncAttributeMaxDynamicSharedMemorySize, fusedSmem);

    int fusedGrid = (N + 127) / 128;
    int scanBlocks = (SEGS + 1023) / 1024;
    int n2 = N * 32;
    int initGrid = (n2 > SEGS ? n2 : SEGS);
    initGrid = (initGrid + 255) / 256;

    // ---- fused init + CSR build (graph identical in both layers) ----
    init_kernel<<<initGrid, 256>>>(x, xbp, n2);
    hist_kernel<<<(E + 255) / 256, 256>>>(dst, rel, E);
    scan_lb_kernel<<<scanBlocks, 1024>>>(SEGS);
    scatter_kernel<<<(E + 255) / 256, 256>>>(src, dst, rel, E);

    int aggGrid = SEGS / 32;

    // ---- layer 1 ----
    aggregate_kernel<<<aggGrid, 256>>>(xbp);
    fused_layer_kernel<<<fusedGrid, 256, fusedSmem>>>(
        xbp, Sp, c1w, c1b, c1ws, c1bs,
        xbp, h1pw, h1pb, h1tw, h1tb,
        nullptr, g1bp, h1bp, N);

    // ---- layer 2 ----
    aggregate_kernel<<<aggGrid, 256>>>(g1bp);
    fused_layer_kernel<<<fusedGrid, 256, fusedSmem>>>(
        g1bp, Sp, c2w, c2b, c2ws, c2bs,
        h1bp, h2pw, h2pb, h2tw, h2tb,
        out, nullptr, nullptr, N);
}